// round 11
// baseline (speedup 1.0000x reference)
#include <cuda_runtime.h>
#include <cuda_bf16.h>
#include <math.h>
#include <stdint.h>

// ----------------------------------------------------------------------------
// MultiScaleDecoder, mma.sync bf16 (tcgen05 unavailable: harness targets sm_100).
//   prep_weights: dense_w transpose->bf16, w1/w2 ->bf16 (one launch)
//   L1: relu(A @ Wd^T) M=49152 N=512 K=512, A read DIRECTLY from fp32 inputs
//   L2: relu(X1 @ w1^T) M=65536 N=256 K=384  (hi-occupancy cfg: 64x128, 3 CTA/SM)
//   L3: relu(X2 @ w2^T) M=262144 N=128 K=64  (hi-occupancy cfg)
//   L4: sigmoid head, smem-staged coalesced output
// ----------------------------------------------------------------------------

#define NP 16384
#define L1_M (3 * NP)                 // 49152
#define X1_ROWS (NP * 4)              // 65536
#define X2_ROWS (NP * 16)             // 262144
#define X3_ROWS (NP * 64)             // 1048576

__device__ __align__(256) __nv_bfloat16 g_X1[(size_t)X1_ROWS * 384];
__device__ __align__(256) __nv_bfloat16 g_X2[(size_t)X2_ROWS * 64];
__device__ __align__(256) __nv_bfloat16 g_X3[(size_t)X3_ROWS * 32];
__device__ __align__(256) __nv_bfloat16 g_Wd[512 * 512];   // [n][k]
__device__ __align__(256) __nv_bfloat16 g_W1[256 * 384];   // [n][k]
__device__ __align__(256) __nv_bfloat16 g_W2[128 * 64];    // [n][k]

// ---------------------------------------------------------------- utils
__device__ __forceinline__ uint32_t smem_u32(const void* p) {
    return (uint32_t)__cvta_generic_to_shared(p);
}
__device__ __forceinline__ void ldsm4(uint32_t& r0, uint32_t& r1, uint32_t& r2,
                                      uint32_t& r3, uint32_t addr) {
    asm volatile("ldmatrix.sync.aligned.m8n8.x4.shared.b16 {%0,%1,%2,%3}, [%4];\n"
                 : "=r"(r0), "=r"(r1), "=r"(r2), "=r"(r3) : "r"(addr));
}
__device__ __forceinline__ void mma16816(float* c, const uint32_t* a,
                                         const uint32_t* b) {
    asm volatile(
        "mma.sync.aligned.m16n8k16.row.col.f32.bf16.bf16.f32 "
        "{%0,%1,%2,%3}, {%4,%5,%6,%7}, {%8,%9}, {%0,%1,%2,%3};\n"
        : "+f"(c[0]), "+f"(c[1]), "+f"(c[2]), "+f"(c[3])
        : "r"(a[0]), "r"(a[1]), "r"(a[2]), "r"(a[3]), "r"(b[0]), "r"(b[1]));
}
__device__ __forceinline__ void cp16(void* sdst, const void* gsrc) {
    asm volatile("cp.async.cg.shared.global [%0], [%1], 16;\n" ::
                 "r"(smem_u32(sdst)), "l"(gsrc));
}

#define BM 128
#define BN 128
#define BK 32
#define LDP 40  // 80B row stride -> conflict-free ldmatrix phases

// ----------------------------------------------------------------------------
// One-launch weight prep.
// ----------------------------------------------------------------------------
__global__ __launch_bounds__(256)
void prep_weights(const float* __restrict__ dw, const float* __restrict__ w1,
                  const float* __restrict__ w2, __nv_bfloat16* __restrict__ wd,
                  __nv_bfloat16* __restrict__ w1b, __nv_bfloat16* __restrict__ w2b)
{
    const int b = blockIdx.x, tid = threadIdx.x;
    if (b < 256) {
        __shared__ float t[32][33];
        const int n0 = (b & 15) * 32, k0 = (b >> 4) * 32;
        const int tx = tid & 31, ty = tid >> 5;
        for (int r = ty; r < 32; r += 8) t[r][tx] = dw[(k0 + r) * 512 + n0 + tx];
        __syncthreads();
        for (int r = ty; r < 32; r += 8)
            wd[(size_t)(n0 + r) * 512 + k0 + tx] = __float2bfloat16(t[tx][r]);
    } else if (b < 352) {
        const int i = ((b - 256) * 256 + tid) * 4;
        float4 v = *reinterpret_cast<const float4*>(w1 + i);
        *reinterpret_cast<__nv_bfloat162*>(w1b + i)     = __floats2bfloat162_rn(v.x, v.y);
        *reinterpret_cast<__nv_bfloat162*>(w1b + i + 2) = __floats2bfloat162_rn(v.z, v.w);
    } else {
        const int i = ((b - 352) * 256 + tid) * 4;
        float4 v = *reinterpret_cast<const float4*>(w2 + i);
        *reinterpret_cast<__nv_bfloat162*>(w2b + i)     = __floats2bfloat162_rn(v.x, v.y);
        *reinterpret_cast<__nv_bfloat162*>(w2b + i + 2) = __floats2bfloat162_rn(v.z, v.w);
    }
}

// ----------------------------------------------------------------------------
// L1: A from fp32 inputs (LDG+convert+STS, register double buffer),
// B via cp.async. 128x128, warp 64x32, K=512. Unchanged from R10 (works).
// ----------------------------------------------------------------------------
__global__ __launch_bounds__(256, 2)
void mma_gemm_l1(const float* __restrict__ A0, const float* __restrict__ A1,
                 const float* __restrict__ A2,
                 const __nv_bfloat16* __restrict__ B,
                 const float* __restrict__ bias,
                 __nv_bfloat16* __restrict__ Out)
{
    constexpr int K = 512;
    __shared__ __align__(16) __nv_bfloat16 As[2][BM * LDP];
    __shared__ __align__(16) __nv_bfloat16 Bs[2][BN * LDP];

    const int tid = threadIdx.x;
    const int warp = tid >> 5, lane = tid & 31;
    const int row0 = blockIdx.y * BM;
    const int col0 = blockIdx.x * BN;
    const int wm = (warp >> 2) * 64;
    const int wn = (warp & 3) * 32;

    const int s = row0 >> 14;
    const float* Abase = (s == 0) ? A0 : (s == 1) ? A1 : A2;
    const int lrow0 = row0 & (NP - 1);

    auto ldgA = [&](int ko, float4 (&ra)[2][2]) {
        #pragma unroll
        for (int c = 0; c < 2; c++) {
            const int r = (tid >> 2) + c * 64;
            const int cc = (tid & 3) * 8;
            const float* p = Abase + (size_t)(lrow0 + r) * K + ko + cc;
            ra[c][0] = *reinterpret_cast<const float4*>(p);
            ra[c][1] = *reinterpret_cast<const float4*>(p + 4);
        }
    };
    auto stsA = [&](int buf, const float4 (&ra)[2][2]) {
        #pragma unroll
        for (int c = 0; c < 2; c++) {
            const int r = (tid >> 2) + c * 64;
            const int cc = (tid & 3) * 8;
            uint4 pk;
            __nv_bfloat162 h;
            h = __floats2bfloat162_rn(ra[c][0].x, ra[c][0].y); pk.x = *(const uint32_t*)&h;
            h = __floats2bfloat162_rn(ra[c][0].z, ra[c][0].w); pk.y = *(const uint32_t*)&h;
            h = __floats2bfloat162_rn(ra[c][1].x, ra[c][1].y); pk.z = *(const uint32_t*)&h;
            h = __floats2bfloat162_rn(ra[c][1].z, ra[c][1].w); pk.w = *(const uint32_t*)&h;
            *reinterpret_cast<uint4*>(&As[buf][r * LDP + cc]) = pk;
        }
    };
    auto loadB = [&](int buf, int ko) {
        #pragma unroll
        for (int c = 0; c < 2; c++) {
            const int ch = tid + c * 256;
            const int r = ch >> 2, cc = (ch & 3) * 8;
            cp16(&Bs[buf][r * LDP + cc], &B[(size_t)(col0 + r) * K + ko + cc]);
        }
        asm volatile("cp.async.commit_group;\n");
    };

    float acc[4][4][4];
    #pragma unroll
    for (int i = 0; i < 4; i++)
        #pragma unroll
        for (int j = 0; j < 4; j++)
            #pragma unroll
            for (int q = 0; q < 4; q++) acc[i][j][q] = 0.f;

    float4 ra[2][2];
    ldgA(0, ra);
    loadB(0, 0);

    for (int it = 0; it < 16; it++) {
        const int sb = it & 1;
        stsA(sb, ra);
        if (it + 1 < 16) {
            ldgA((it + 1) * BK, ra);
            loadB((it + 1) & 1, (it + 1) * BK);
            asm volatile("cp.async.wait_group 1;\n");
        } else {
            asm volatile("cp.async.wait_group 0;\n");
        }
        __syncthreads();

        #pragma unroll
        for (int ks = 0; ks < 2; ks++) {
            const int k0 = ks * 16;
            uint32_t a[4][4], b[4][2];
            #pragma unroll
            for (int i = 0; i < 4; i++) {
                int r = wm + i * 16 + (lane & 15);
                int kk = k0 + ((lane >> 4) << 3);
                ldsm4(a[i][0], a[i][1], a[i][2], a[i][3],
                      smem_u32(&As[sb][r * LDP + kk]));
            }
            #pragma unroll
            for (int jp = 0; jp < 2; jp++) {
                int rB = wn + jp * 16 + ((lane >> 4) << 3) + (lane & 7);
                int kk = k0 + (((lane >> 3) & 1) << 3);
                ldsm4(b[2 * jp][0], b[2 * jp][1], b[2 * jp + 1][0], b[2 * jp + 1][1],
                      smem_u32(&Bs[sb][rB * LDP + kk]));
            }
            #pragma unroll
            for (int i = 0; i < 4; i++)
                #pragma unroll
                for (int j = 0; j < 4; j++) mma16816(acc[i][j], a[i], b[j]);
        }
        __syncthreads();
    }

    #pragma unroll
    for (int i = 0; i < 4; i++) {
        const int mA = row0 + wm + i * 16 + (lane >> 2);
        #pragma unroll
        for (int j = 0; j < 4; j++) {
            const int nA = col0 + wn + j * 8 + 2 * (lane & 3);
            #pragma unroll
            for (int hh = 0; hh < 2; hh++) {
                const int row = mA + hh * 8;
                const float v0 = fmaxf(acc[i][j][2 * hh]     + bias[nA],     0.f);
                const float v1 = fmaxf(acc[i][j][2 * hh + 1] + bias[nA + 1], 0.f);
                const int pos = nA >> 7, kc = nA & 127;
                const int nl = row & (NP - 1);
                const size_t addr = ((size_t)(nl * 4 + pos)) * 384 + s * 128 + kc;
                *reinterpret_cast<__nv_bfloat162*>(&Out[addr]) =
                    __floats2bfloat162_rn(v0, v1);
            }
        }
    }
}

// ----------------------------------------------------------------------------
// Hi-occupancy GEMM for L2/L3: BM=64, BN=128, warp tile 32x32 (2x4 warps),
// acc 32 regs/thread, __launch_bounds__(256,3) -> 3 CTAs/SM.
// EPI: 2 = deconv1->X2 scatter, 3 = deconv2->X3 scatter
// ----------------------------------------------------------------------------
#define HBM_ 64
#define HBN_ 128

template <int EPI>
__global__ __launch_bounds__(256, 3)
void mma_gemm_hi(const __nv_bfloat16* __restrict__ A,
                 const __nv_bfloat16* __restrict__ B,
                 const float* __restrict__ bias,
                 __nv_bfloat16* __restrict__ Out, int K)
{
    __shared__ __align__(16) __nv_bfloat16 As[2][HBM_ * LDP];
    __shared__ __align__(16) __nv_bfloat16 Bs[2][HBN_ * LDP];

    const int tid = threadIdx.x;
    const int warp = tid >> 5, lane = tid & 31;
    const int row0 = blockIdx.y * HBM_;
    const int col0 = blockIdx.x * HBN_;
    const int wm = (warp >> 2) * 32;   // 2 warp-rows
    const int wn = (warp & 3) * 32;    // 4 warp-cols
    const int NIT = K / BK;

    auto load_stage = [&](int buf, int ko) {
        {   // A: 64 rows x 32 cols = 256 chunks, 1/thread
            int r = tid >> 2, cc = (tid & 3) * 8;
            cp16(&As[buf][r * LDP + cc], &A[(size_t)(row0 + r) * K + ko + cc]);
        }
        #pragma unroll
        for (int c = 0; c < 2; c++) {   // B: 128 rows = 512 chunks
            int ch = tid + c * 256;
            int r = ch >> 2, cc = (ch & 3) * 8;
            cp16(&Bs[buf][r * LDP + cc], &B[(size_t)(col0 + r) * K + ko + cc]);
        }
        asm volatile("cp.async.commit_group;\n");
    };

    float acc[2][4][4];
    #pragma unroll
    for (int i = 0; i < 2; i++)
        #pragma unroll
        for (int j = 0; j < 4; j++)
            #pragma unroll
            for (int q = 0; q < 4; q++) acc[i][j][q] = 0.f;

    load_stage(0, 0);

    for (int it = 0; it < NIT; it++) {
        if (it + 1 < NIT) {
            load_stage((it + 1) & 1, (it + 1) * BK);
            asm volatile("cp.async.wait_group 1;\n");
        } else {
            asm volatile("cp.async.wait_group 0;\n");
        }
        __syncthreads();

        const int sb = it & 1;
        #pragma unroll
        for (int ks = 0; ks < 2; ks++) {
            const int k0 = ks * 16;
            uint32_t a[2][4], b[4][2];
            #pragma unroll
            for (int i = 0; i < 2; i++) {
                int r = wm + i * 16 + (lane & 15);
                int kk = k0 + ((lane >> 4) << 3);
                ldsm4(a[i][0], a[i][1], a[i][2], a[i][3],
                      smem_u32(&As[sb][r * LDP + kk]));
            }
            #pragma unroll
            for (int jp = 0; jp < 2; jp++) {
                int rB = wn + jp * 16 + ((lane >> 4) << 3) + (lane & 7);
                int kk = k0 + (((lane >> 3) & 1) << 3);
                ldsm4(b[2 * jp][0], b[2 * jp][1], b[2 * jp + 1][0], b[2 * jp + 1][1],
                      smem_u32(&Bs[sb][rB * LDP + kk]));
            }
            #pragma unroll
            for (int i = 0; i < 2; i++)
                #pragma unroll
                for (int j = 0; j < 4; j++) mma16816(acc[i][j], a[i], b[j]);
        }
        __syncthreads();
    }

    auto epi_store = [&](int row, int col, float v0, float v1) {
        float b0, b1;
        if (EPI == 2) { b0 = bias[col & 63]; b1 = bias[(col & 63) + 1]; }
        else          { b0 = bias[col & 31]; b1 = bias[(col & 31) + 1]; }
        v0 = fmaxf(v0 + b0, 0.f);
        v1 = fmaxf(v1 + b1, 0.f);
        size_t addr;
        if (EPI == 2) {
            const int a_ = col >> 7, c_ = (col >> 6) & 1, f = col & 63;
            const int nn = row >> 2, ii = (row >> 1) & 1, jj = row & 1;
            addr = ((size_t)(nn * 16 + (2 * ii + a_) * 4 + (2 * jj + c_))) * 64 + f;
        } else {
            const int a_ = col >> 6, c_ = (col >> 5) & 1, f = col & 31;
            const int nn = row >> 4, p = (row >> 2) & 3, q = row & 3;
            addr = ((size_t)(nn * 64 + (2 * p + a_) * 8 + (2 * q + c_))) * 32 + f;
        }
        *reinterpret_cast<__nv_bfloat162*>(&Out[addr]) = __floats2bfloat162_rn(v0, v1);
    };

    #pragma unroll
    for (int i = 0; i < 2; i++) {
        const int mA = row0 + wm + i * 16 + (lane >> 2);
        #pragma unroll
        for (int j = 0; j < 4; j++) {
            const int nA = col0 + wn + j * 8 + 2 * (lane & 3);
            epi_store(mA,     nA, acc[i][j][0], acc[i][j][1]);
            epi_store(mA + 8, nA, acc[i][j][2], acc[i][j][3]);
        }
    }
}

// ---------------------------------------------------------------- layer 4
__global__ __launch_bounds__(256)
void layer4_kernel(const __nv_bfloat16* __restrict__ X3,
                   const float* __restrict__ w3, const float* __restrict__ b3,
                   float* __restrict__ out)
{
    __shared__ __align__(16) float ostage[6144];
    __shared__ float ws[384];
    __shared__ float bsm[3];

    const int tid = threadIdx.x;
    for (int i = tid; i < 384; i += 256) ws[i] = w3[i];
    if (tid < 3) bsm[tid] = b3[tid];
    __syncthreads();

    const int r0 = blockIdx.x * 512;

    #pragma unroll
    for (int h = 0; h < 2; h++) {
        const int rl = tid + h * 256;
        const int r  = r0 + rl;
        uint4 xr[4];
        const uint4* xp = reinterpret_cast<const uint4*>(X3 + (size_t)r * 32);
        #pragma unroll
        for (int i = 0; i < 4; i++) xr[i] = xp[i];
        float x[32];
        #pragma unroll
        for (int i = 0; i < 16; i++) {
            __nv_bfloat162 pr = reinterpret_cast<const __nv_bfloat162*>(xr)[i];
            float2 f2 = __bfloat1622float2(pr);
            x[2 * i] = f2.x; x[2 * i + 1] = f2.y;
        }
        const int nl = rl >> 6, P = (rl >> 3) & 7, Q = rl & 7;
        const int obase = nl * 768;
        #pragma unroll
        for (int o = 0; o < 12; o++) {
            float acc = bsm[o % 3];
            #pragma unroll
            for (int k = 0; k < 32; k++) acc = fmaf(x[k], ws[o * 32 + k], acc);
            const float v = 1.f / (1.f + __expf(-acc));
            const int a2 = o / 6, c2 = (o / 3) & 1, ch = o % 3;
            ostage[obase + (2 * P + a2) * 48 + (2 * Q + c2) * 3 + ch] = v;
        }
    }
    __syncthreads();

    float4* gout = reinterpret_cast<float4*>(out + (size_t)blockIdx.x * 6144);
    const float4* so = reinterpret_cast<const float4*>(ostage);
    #pragma unroll
    for (int i = 0; i < 6; i++) gout[tid + i * 256] = so[tid + i * 256];
}

// ---------------------------------------------------------------- host entry
extern "C" void kernel_launch(void* const* d_in, const int* in_sizes, int n_in,
                              void* d_out, int out_size)
{
    const float* in1     = (const float*)d_in[0];
    const float* in2     = (const float*)d_in[1];
    const float* in3     = (const float*)d_in[2];
    const float* dense_w = (const float*)d_in[3];
    const float* dense_b = (const float*)d_in[4];
    const float* w1      = (const float*)d_in[5];
    const float* b1      = (const float*)d_in[6];
    const float* w2      = (const float*)d_in[7];
    const float* b2      = (const float*)d_in[8];
    const float* w3      = (const float*)d_in[9];
    const float* b3      = (const float*)d_in[10];
    float* out           = (float*)d_out;

    __nv_bfloat16 *x1, *x2, *x3, *wd, *w1b, *w2b;
    cudaGetSymbolAddress((void**)&x1, g_X1);
    cudaGetSymbolAddress((void**)&x2, g_X2);
    cudaGetSymbolAddress((void**)&x3, g_X3);
    cudaGetSymbolAddress((void**)&wd, g_Wd);
    cudaGetSymbolAddress((void**)&w1b, g_W1);
    cudaGetSymbolAddress((void**)&w2b, g_W2);

    // one-launch weight prep
    prep_weights<<<360, 256>>>(dense_w, w1, w2, wd, w1b, w2b);

    // L1: direct-from-fp32 A, grid (4, 384)
    mma_gemm_l1<<<dim3(512 / BN, L1_M / BM), 256>>>(in1, in2, in3, wd,
                                                    dense_b, x1);
    // L2: [65536,384] @ w1^T[384,256]  grid (2, 1024)
    mma_gemm_hi<2><<<dim3(256 / HBN_, X1_ROWS / HBM_), 256>>>(x1, w1b, b1, x2, 384);
    // L3: [262144,64] @ w2^T[64,128]   grid (1, 4096)
    mma_gemm_hi<3><<<dim3(128 / HBN_, X2_ROWS / HBM_), 256>>>(x2, w2b, b2, x3, 64);
    // L4
    layer4_kernel<<<X3_ROWS / 512, 256>>>(x3, w3, b3, out);
}

// round 12
// speedup vs baseline: 1.4271x; 1.4271x over previous
#include <cuda_runtime.h>
#include <cuda_bf16.h>
#include <math.h>
#include <stdint.h>

// ----------------------------------------------------------------------------
// MultiScaleDecoder, mma.sync bf16 (tcgen05 unavailable: harness targets sm_100).
//   prep_weights: dense_w transpose->bf16, w1/w2 ->bf16 (one launch)
//   L1: relu(A @ Wd^T) M=49152 N=512 K=512, A read DIRECTLY from fp32 inputs
//   L2: relu(X1 @ w1^T) M=65536 N=256 K=384  (hi-occ 64x128 cfg)
//   L3+L4 FUSED: per CTA = 64 X2 rows = 4 patches:
//        GEMM 64x128x64 -> bf16 stage in smem (aliases dead pipeline bufs)
//        -> w3 + sigmoid tail -> fp32 ostage -> coalesced float4 flush.
//        X3 never touches HBM (saves 134 MB round trip + one launch).
// ----------------------------------------------------------------------------

#define NP 16384
#define L1_M (3 * NP)                 // 49152
#define X1_ROWS (NP * 4)              // 65536
#define X2_ROWS (NP * 16)             // 262144

__device__ __align__(256) __nv_bfloat16 g_X1[(size_t)X1_ROWS * 384];
__device__ __align__(256) __nv_bfloat16 g_X2[(size_t)X2_ROWS * 64];
__device__ __align__(256) __nv_bfloat16 g_Wd[512 * 512];   // [n][k]
__device__ __align__(256) __nv_bfloat16 g_W1[256 * 384];   // [n][k]
__device__ __align__(256) __nv_bfloat16 g_W2[128 * 64];    // [n][k]

// ---------------------------------------------------------------- utils
__device__ __forceinline__ uint32_t smem_u32(const void* p) {
    return (uint32_t)__cvta_generic_to_shared(p);
}
__device__ __forceinline__ void ldsm4(uint32_t& r0, uint32_t& r1, uint32_t& r2,
                                      uint32_t& r3, uint32_t addr) {
    asm volatile("ldmatrix.sync.aligned.m8n8.x4.shared.b16 {%0,%1,%2,%3}, [%4];\n"
                 : "=r"(r0), "=r"(r1), "=r"(r2), "=r"(r3) : "r"(addr));
}
__device__ __forceinline__ void mma16816(float* c, const uint32_t* a,
                                         const uint32_t* b) {
    asm volatile(
        "mma.sync.aligned.m16n8k16.row.col.f32.bf16.bf16.f32 "
        "{%0,%1,%2,%3}, {%4,%5,%6,%7}, {%8,%9}, {%0,%1,%2,%3};\n"
        : "+f"(c[0]), "+f"(c[1]), "+f"(c[2]), "+f"(c[3])
        : "r"(a[0]), "r"(a[1]), "r"(a[2]), "r"(a[3]), "r"(b[0]), "r"(b[1]));
}
__device__ __forceinline__ void cp16(void* sdst, const void* gsrc) {
    asm volatile("cp.async.cg.shared.global [%0], [%1], 16;\n" ::
                 "r"(smem_u32(sdst)), "l"(gsrc));
}

#define BM 128
#define BN 128
#define BK 32
#define LDP 40  // 80B row stride -> conflict-free ldmatrix / LDS.128 phases

// ----------------------------------------------------------------------------
// One-launch weight prep.
// ----------------------------------------------------------------------------
__global__ __launch_bounds__(256)
void prep_weights(const float* __restrict__ dw, const float* __restrict__ w1,
                  const float* __restrict__ w2, __nv_bfloat16* __restrict__ wd,
                  __nv_bfloat16* __restrict__ w1b, __nv_bfloat16* __restrict__ w2b)
{
    const int b = blockIdx.x, tid = threadIdx.x;
    if (b < 256) {
        __shared__ float t[32][33];
        const int n0 = (b & 15) * 32, k0 = (b >> 4) * 32;
        const int tx = tid & 31, ty = tid >> 5;
        for (int r = ty; r < 32; r += 8) t[r][tx] = dw[(k0 + r) * 512 + n0 + tx];
        __syncthreads();
        for (int r = ty; r < 32; r += 8)
            wd[(size_t)(n0 + r) * 512 + k0 + tx] = __float2bfloat16(t[tx][r]);
    } else if (b < 352) {
        const int i = ((b - 256) * 256 + tid) * 4;
        float4 v = *reinterpret_cast<const float4*>(w1 + i);
        *reinterpret_cast<__nv_bfloat162*>(w1b + i)     = __floats2bfloat162_rn(v.x, v.y);
        *reinterpret_cast<__nv_bfloat162*>(w1b + i + 2) = __floats2bfloat162_rn(v.z, v.w);
    } else {
        const int i = ((b - 352) * 256 + tid) * 4;
        float4 v = *reinterpret_cast<const float4*>(w2 + i);
        *reinterpret_cast<__nv_bfloat162*>(w2b + i)     = __floats2bfloat162_rn(v.x, v.y);
        *reinterpret_cast<__nv_bfloat162*>(w2b + i + 2) = __floats2bfloat162_rn(v.z, v.w);
    }
}

// ----------------------------------------------------------------------------
// L1: A from fp32 inputs (LDG+convert+STS, register double buffer),
// B via cp.async. 128x128, warp 64x32, K=512. Unchanged (proven).
// ----------------------------------------------------------------------------
__global__ __launch_bounds__(256, 2)
void mma_gemm_l1(const float* __restrict__ A0, const float* __restrict__ A1,
                 const float* __restrict__ A2,
                 const __nv_bfloat16* __restrict__ B,
                 const float* __restrict__ bias,
                 __nv_bfloat16* __restrict__ Out)
{
    constexpr int K = 512;
    __shared__ __align__(16) __nv_bfloat16 As[2][BM * LDP];
    __shared__ __align__(16) __nv_bfloat16 Bs[2][BN * LDP];

    const int tid = threadIdx.x;
    const int warp = tid >> 5, lane = tid & 31;
    const int row0 = blockIdx.y * BM;
    const int col0 = blockIdx.x * BN;
    const int wm = (warp >> 2) * 64;
    const int wn = (warp & 3) * 32;

    const int s = row0 >> 14;
    const float* Abase = (s == 0) ? A0 : (s == 1) ? A1 : A2;
    const int lrow0 = row0 & (NP - 1);

    auto ldgA = [&](int ko, float4 (&ra)[2][2]) {
        #pragma unroll
        for (int c = 0; c < 2; c++) {
            const int r = (tid >> 2) + c * 64;
            const int cc = (tid & 3) * 8;
            const float* p = Abase + (size_t)(lrow0 + r) * K + ko + cc;
            ra[c][0] = *reinterpret_cast<const float4*>(p);
            ra[c][1] = *reinterpret_cast<const float4*>(p + 4);
        }
    };
    auto stsA = [&](int buf, const float4 (&ra)[2][2]) {
        #pragma unroll
        for (int c = 0; c < 2; c++) {
            const int r = (tid >> 2) + c * 64;
            const int cc = (tid & 3) * 8;
            uint4 pk;
            __nv_bfloat162 h;
            h = __floats2bfloat162_rn(ra[c][0].x, ra[c][0].y); pk.x = *(const uint32_t*)&h;
            h = __floats2bfloat162_rn(ra[c][0].z, ra[c][0].w); pk.y = *(const uint32_t*)&h;
            h = __floats2bfloat162_rn(ra[c][1].x, ra[c][1].y); pk.z = *(const uint32_t*)&h;
            h = __floats2bfloat162_rn(ra[c][1].z, ra[c][1].w); pk.w = *(const uint32_t*)&h;
            *reinterpret_cast<uint4*>(&As[buf][r * LDP + cc]) = pk;
        }
    };
    auto loadB = [&](int buf, int ko) {
        #pragma unroll
        for (int c = 0; c < 2; c++) {
            const int ch = tid + c * 256;
            const int r = ch >> 2, cc = (ch & 3) * 8;
            cp16(&Bs[buf][r * LDP + cc], &B[(size_t)(col0 + r) * K + ko + cc]);
        }
        asm volatile("cp.async.commit_group;\n");
    };

    float acc[4][4][4];
    #pragma unroll
    for (int i = 0; i < 4; i++)
        #pragma unroll
        for (int j = 0; j < 4; j++)
            #pragma unroll
            for (int q = 0; q < 4; q++) acc[i][j][q] = 0.f;

    float4 ra[2][2];
    ldgA(0, ra);
    loadB(0, 0);

    for (int it = 0; it < 16; it++) {
        const int sb = it & 1;
        stsA(sb, ra);
        if (it + 1 < 16) {
            ldgA((it + 1) * BK, ra);
            loadB((it + 1) & 1, (it + 1) * BK);
            asm volatile("cp.async.wait_group 1;\n");
        } else {
            asm volatile("cp.async.wait_group 0;\n");
        }
        __syncthreads();

        #pragma unroll
        for (int ks = 0; ks < 2; ks++) {
            const int k0 = ks * 16;
            uint32_t a[4][4], b[4][2];
            #pragma unroll
            for (int i = 0; i < 4; i++) {
                int r = wm + i * 16 + (lane & 15);
                int kk = k0 + ((lane >> 4) << 3);
                ldsm4(a[i][0], a[i][1], a[i][2], a[i][3],
                      smem_u32(&As[sb][r * LDP + kk]));
            }
            #pragma unroll
            for (int jp = 0; jp < 2; jp++) {
                int rB = wn + jp * 16 + ((lane >> 4) << 3) + (lane & 7);
                int kk = k0 + (((lane >> 3) & 1) << 3);
                ldsm4(b[2 * jp][0], b[2 * jp][1], b[2 * jp + 1][0], b[2 * jp + 1][1],
                      smem_u32(&Bs[sb][rB * LDP + kk]));
            }
            #pragma unroll
            for (int i = 0; i < 4; i++)
                #pragma unroll
                for (int j = 0; j < 4; j++) mma16816(acc[i][j], a[i], b[j]);
        }
        __syncthreads();
    }

    #pragma unroll
    for (int i = 0; i < 4; i++) {
        const int mA = row0 + wm + i * 16 + (lane >> 2);
        #pragma unroll
        for (int j = 0; j < 4; j++) {
            const int nA = col0 + wn + j * 8 + 2 * (lane & 3);
            #pragma unroll
            for (int hh = 0; hh < 2; hh++) {
                const int row = mA + hh * 8;
                const float v0 = fmaxf(acc[i][j][2 * hh]     + bias[nA],     0.f);
                const float v1 = fmaxf(acc[i][j][2 * hh + 1] + bias[nA + 1], 0.f);
                const int pos = nA >> 7, kc = nA & 127;
                const int nl = row & (NP - 1);
                const size_t addr = ((size_t)(nl * 4 + pos)) * 384 + s * 128 + kc;
                *reinterpret_cast<__nv_bfloat162*>(&Out[addr]) =
                    __floats2bfloat162_rn(v0, v1);
            }
        }
    }
}

// ----------------------------------------------------------------------------
// Hi-occupancy GEMM for L2: BM=64, BN=128, warp 32x32 (2x4 warps).
// ----------------------------------------------------------------------------
#define HBM_ 64
#define HBN_ 128

__global__ __launch_bounds__(256, 3)
void mma_gemm_l2(const __nv_bfloat16* __restrict__ A,
                 const __nv_bfloat16* __restrict__ B,
                 const float* __restrict__ bias,
                 __nv_bfloat16* __restrict__ Out)
{
    constexpr int K = 384;
    __shared__ __align__(16) __nv_bfloat16 As[2][HBM_ * LDP];
    __shared__ __align__(16) __nv_bfloat16 Bs[2][HBN_ * LDP];

    const int tid = threadIdx.x;
    const int warp = tid >> 5, lane = tid & 31;
    const int row0 = blockIdx.y * HBM_;
    const int col0 = blockIdx.x * HBN_;
    const int wm = (warp >> 2) * 32;
    const int wn = (warp & 3) * 32;
    const int NIT = K / BK;   // 12

    auto load_stage = [&](int buf, int ko) {
        {
            int r = tid >> 2, cc = (tid & 3) * 8;
            cp16(&As[buf][r * LDP + cc], &A[(size_t)(row0 + r) * K + ko + cc]);
        }
        #pragma unroll
        for (int c = 0; c < 2; c++) {
            int ch = tid + c * 256;
            int r = ch >> 2, cc = (ch & 3) * 8;
            cp16(&Bs[buf][r * LDP + cc], &B[(size_t)(col0 + r) * K + ko + cc]);
        }
        asm volatile("cp.async.commit_group;\n");
    };

    float acc[2][4][4];
    #pragma unroll
    for (int i = 0; i < 2; i++)
        #pragma unroll
        for (int j = 0; j < 4; j++)
            #pragma unroll
            for (int q = 0; q < 4; q++) acc[i][j][q] = 0.f;

    load_stage(0, 0);

    for (int it = 0; it < NIT; it++) {
        if (it + 1 < NIT) {
            load_stage((it + 1) & 1, (it + 1) * BK);
            asm volatile("cp.async.wait_group 1;\n");
        } else {
            asm volatile("cp.async.wait_group 0;\n");
        }
        __syncthreads();

        const int sb = it & 1;
        #pragma unroll
        for (int ks = 0; ks < 2; ks++) {
            const int k0 = ks * 16;
            uint32_t a[2][4], b[4][2];
            #pragma unroll
            for (int i = 0; i < 2; i++) {
                int r = wm + i * 16 + (lane & 15);
                int kk = k0 + ((lane >> 4) << 3);
                ldsm4(a[i][0], a[i][1], a[i][2], a[i][3],
                      smem_u32(&As[sb][r * LDP + kk]));
            }
            #pragma unroll
            for (int jp = 0; jp < 2; jp++) {
                int rB = wn + jp * 16 + ((lane >> 4) << 3) + (lane & 7);
                int kk = k0 + (((lane >> 3) & 1) << 3);
                ldsm4(b[2 * jp][0], b[2 * jp][1], b[2 * jp + 1][0], b[2 * jp + 1][1],
                      smem_u32(&Bs[sb][rB * LDP + kk]));
            }
            #pragma unroll
            for (int i = 0; i < 2; i++)
                #pragma unroll
                for (int j = 0; j < 4; j++) mma16816(acc[i][j], a[i], b[j]);
        }
        __syncthreads();
    }

    #pragma unroll
    for (int i = 0; i < 2; i++) {
        const int mA = row0 + wm + i * 16 + (lane >> 2);
        #pragma unroll
        for (int j = 0; j < 4; j++) {
            const int nA = col0 + wn + j * 8 + 2 * (lane & 3);
            #pragma unroll
            for (int hh = 0; hh < 2; hh++) {
                const int row = mA + hh * 8;
                const float v0 = fmaxf(acc[i][j][2 * hh]     + bias[nA & 63], 0.f);
                const float v1 = fmaxf(acc[i][j][2 * hh + 1] + bias[(nA & 63) + 1], 0.f);
                const int a_ = nA >> 7, c_ = (nA >> 6) & 1, f = nA & 63;
                const int nn = row >> 2, ii = (row >> 1) & 1, jj = row & 1;
                const size_t addr =
                    ((size_t)(nn * 16 + (2 * ii + a_) * 4 + (2 * jj + c_))) * 64 + f;
                *reinterpret_cast<__nv_bfloat162*>(&Out[addr]) =
                    __floats2bfloat162_rn(v0, v1);
            }
        }
    }
}

// ----------------------------------------------------------------------------
// Fused L3+L4. One CTA = 64 X2 rows = 4 patches.
//   Phase 1: GEMM 64x128x64 (hi-occ cfg, 2 K-iters) -> acc regs
//   Phase 2: bias+relu -> bf16 stage[256][40] in smem (aliases dead pipe bufs)
//   Phase 3: per-thread w3 dot + sigmoid -> fp32 ostage (non-aliasing region)
//   Phase 4: coalesced float4 flush (4 patches * 768 floats contiguous)
// smem: max(pipe 30720, stage 20480 + ostage 12288) = 32768 B -> static union.
// ----------------------------------------------------------------------------
#define F34_SMEM 32768

__global__ __launch_bounds__(256, 2)
void l3_l4_fused(const __nv_bfloat16* __restrict__ A,    // X2
                 const __nv_bfloat16* __restrict__ B,    // W2 [128][64]
                 const float* __restrict__ b2,
                 const float* __restrict__ w3, const float* __restrict__ b3,
                 float* __restrict__ out)
{
    __shared__ __align__(16) uint8_t raw[F34_SMEM];
    __shared__ float ws[384];
    __shared__ float bsm[3];

    __nv_bfloat16* As = reinterpret_cast<__nv_bfloat16*>(raw);              // [2][64*40]
    __nv_bfloat16* Bs = reinterpret_cast<__nv_bfloat16*>(raw + 10240);      // [2][128*40]
    __nv_bfloat16* stage = reinterpret_cast<__nv_bfloat16*>(raw);           // [256][40]
    float* ostage = reinterpret_cast<float*>(raw + 20480);                  // [3072]

    const int tid = threadIdx.x;
    const int warp = tid >> 5, lane = tid & 31;
    const int row0 = blockIdx.x * HBM_;       // X2 row base (4 patches)
    const int wm = (warp >> 2) * 32;
    const int wn = (warp & 3) * 32;

    for (int i = tid; i < 384; i += 256) ws[i] = w3[i];
    if (tid < 3) bsm[tid] = b3[tid];

    auto load_stage = [&](int buf, int ko) {
        {
            int r = tid >> 2, cc = (tid & 3) * 8;
            cp16(&As[buf * (HBM_ * LDP) + r * LDP + cc],
                 &A[(size_t)(row0 + r) * 64 + ko + cc]);
        }
        #pragma unroll
        for (int c = 0; c < 2; c++) {
            int ch = tid + c * 256;
            int r = ch >> 2, cc = (ch & 3) * 8;
            cp16(&Bs[buf * (HBN_ * LDP) + r * LDP + cc],
                 &B[(size_t)r * 64 + ko + cc]);
        }
        asm volatile("cp.async.commit_group;\n");
    };

    float acc[2][4][4];
    #pragma unroll
    for (int i = 0; i < 2; i++)
        #pragma unroll
        for (int j = 0; j < 4; j++)
            #pragma unroll
            for (int q = 0; q < 4; q++) acc[i][j][q] = 0.f;

    load_stage(0, 0);
    load_stage(1, BK);

    #pragma unroll
    for (int it = 0; it < 2; it++) {
        if (it == 0) asm volatile("cp.async.wait_group 1;\n");
        else         asm volatile("cp.async.wait_group 0;\n");
        __syncthreads();

        const int sb = it;
        #pragma unroll
        for (int ks = 0; ks < 2; ks++) {
            const int k0 = ks * 16;
            uint32_t a[2][4], b[4][2];
            #pragma unroll
            for (int i = 0; i < 2; i++) {
                int r = wm + i * 16 + (lane & 15);
                int kk = k0 + ((lane >> 4) << 3);
                ldsm4(a[i][0], a[i][1], a[i][2], a[i][3],
                      smem_u32(&As[sb * (HBM_ * LDP) + r * LDP + kk]));
            }
            #pragma unroll
            for (int jp = 0; jp < 2; jp++) {
                int rB = wn + jp * 16 + ((lane >> 4) << 3) + (lane & 7);
                int kk = k0 + (((lane >> 3) & 1) << 3);
                ldsm4(b[2 * jp][0], b[2 * jp][1], b[2 * jp + 1][0], b[2 * jp + 1][1],
                      smem_u32(&Bs[sb * (HBN_ * LDP) + rB * LDP + kk]));
            }
            #pragma unroll
            for (int i = 0; i < 2; i++)
                #pragma unroll
                for (int j = 0; j < 4; j++) mma16816(acc[i][j], a[i], b[j]);
        }
        __syncthreads();   // after last iter, pipe buffers are dead
    }

    // Phase 2: bias+relu -> stage (X3 rows local to these 4 patches)
    #pragma unroll
    for (int i = 0; i < 2; i++) {
        const int mL = wm + i * 16 + (lane >> 2);   // local X2 row 0..63
        #pragma unroll
        for (int j = 0; j < 4; j++) {
            const int nA = wn + j * 8 + 2 * (lane & 3);    // 0..127
            const int a_ = nA >> 6, c_ = (nA >> 5) & 1, f = nA & 31;
            #pragma unroll
            for (int hh = 0; hh < 2; hh++) {
                const int r_loc = mL + hh * 8;
                const float v0 = fmaxf(acc[i][j][2 * hh]     + b2[f],     0.f);
                const float v1 = fmaxf(acc[i][j][2 * hh + 1] + b2[f + 1], 0.f);
                const int nl = r_loc >> 4, p = (r_loc >> 2) & 3, q = r_loc & 3;
                const int lrow = nl * 64 + (2 * p + a_) * 8 + (2 * q + c_);
                *reinterpret_cast<__nv_bfloat162*>(&stage[lrow * LDP + f]) =
                    __floats2bfloat162_rn(v0, v1);
            }
        }
    }
    __syncthreads();

    // Phase 3: per-thread X3 row -> 12 sigmoid outputs into ostage
    {
        const int rl = tid;   // 0..255
        uint4 xr[4];
        const uint4* sp = reinterpret_cast<const uint4*>(&stage[rl * LDP]);
        #pragma unroll
        for (int i = 0; i < 4; i++) xr[i] = sp[i];
        __syncthreads();      // stage reads done before ostage writes (no overlap, but cheap safety for reuse discipline)

        float x[32];
        #pragma unroll
        for (int i = 0; i < 16; i++) {
            __nv_bfloat162 pr = reinterpret_cast<const __nv_bfloat162*>(xr)[i];
            float2 f2 = __bfloat1622float2(pr);
            x[2 * i] = f2.x; x[2 * i + 1] = f2.y;
        }
        const int nl = rl >> 6, P = (rl >> 3) & 7, Q = rl & 7;
        const int obase = nl * 768;
        #pragma unroll
        for (int o = 0; o < 12; o++) {
            float accv = bsm[o % 3];
            #pragma unroll
            for (int k = 0; k < 32; k++) accv = fmaf(x[k], ws[o * 32 + k], accv);
            const float v = 1.f / (1.f + __expf(-accv));
            const int a2 = o / 6, c2 = (o / 3) & 1, ch = o % 3;
            ostage[obase + (2 * P + a2) * 48 + (2 * Q + c2) * 3 + ch] = v;
        }
    }
    __syncthreads();

    // Phase 4: coalesced flush — 4 patches * 768 floats contiguous
    float4* gout = reinterpret_cast<float4*>(out + (size_t)blockIdx.x * 3072);
    const float4* so = reinterpret_cast<const float4*>(ostage);
    #pragma unroll
    for (int i = 0; i < 3; i++) gout[tid + i * 256] = so[tid + i * 256];
}

// ---------------------------------------------------------------- host entry
extern "C" void kernel_launch(void* const* d_in, const int* in_sizes, int n_in,
                              void* d_out, int out_size)
{
    const float* in1     = (const float*)d_in[0];
    const float* in2     = (const float*)d_in[1];
    const float* in3     = (const float*)d_in[2];
    const float* dense_w = (const float*)d_in[3];
    const float* dense_b = (const float*)d_in[4];
    const float* w1      = (const float*)d_in[5];
    const float* b1      = (const float*)d_in[6];
    const float* w2      = (const float*)d_in[7];
    const float* b2      = (const float*)d_in[8];
    const float* w3      = (const float*)d_in[9];
    const float* b3      = (const float*)d_in[10];
    float* out           = (float*)d_out;

    __nv_bfloat16 *x1, *x2, *wd, *w1b, *w2b;
    cudaGetSymbolAddress((void**)&x1, g_X1);
    cudaGetSymbolAddress((void**)&x2, g_X2);
    cudaGetSymbolAddress((void**)&wd, g_Wd);
    cudaGetSymbolAddress((void**)&w1b, g_W1);
    cudaGetSymbolAddress((void**)&w2b, g_W2);

    // one-launch weight prep
    prep_weights<<<360, 256>>>(dense_w, w1, w2, wd, w1b, w2b);

    // L1: direct-from-fp32 A, grid (4, 384)
    mma_gemm_l1<<<dim3(512 / BN, L1_M / BM), 256>>>(in1, in2, in3, wd,
                                                    dense_b, x1);
    // L2: [65536,384] @ w1^T[384,256]  grid (2, 1024)
    mma_gemm_l2<<<dim3(256 / HBN_, X1_ROWS / HBM_), 256>>>(x1, w1b, b1, x2);
    // L3+L4 fused: 4096 blocks of 4 patches
    l3_l4_fused<<<X2_ROWS / HBM_, 256>>>(x2, w2b, b2, w3, b3, out);
}

// round 13
// speedup vs baseline: 1.4351x; 1.0056x over previous
#include <cuda_runtime.h>
#include <cuda_bf16.h>
#include <math.h>
#include <stdint.h>

// ----------------------------------------------------------------------------
// MultiScaleDecoder, mma.sync bf16 (tcgen05 unavailable: harness targets sm_100).
//   prep_weights: dense_w transpose->bf16, w1/w2 ->bf16 (one launch)
//   L1: relu(A @ Wd^T) M=49152 N=512 K=512, A DIRECT from fp32 inputs,
//       hi-occ cfg 64x128, 3 CTAs/SM
//   L2: relu(X1 @ w1^T) M=65536 N=256 K=384  (hi-occ 64x128 cfg, 3 CTAs/SM)
//   L3+L4 FUSED (4 patches/CTA, X3 never in HBM), 3 CTAs/SM
// ----------------------------------------------------------------------------

#define NP 16384
#define L1_M (3 * NP)                 // 49152
#define X1_ROWS (NP * 4)              // 65536
#define X2_ROWS (NP * 16)             // 262144

__device__ __align__(256) __nv_bfloat16 g_X1[(size_t)X1_ROWS * 384];
__device__ __align__(256) __nv_bfloat16 g_X2[(size_t)X2_ROWS * 64];
__device__ __align__(256) __nv_bfloat16 g_Wd[512 * 512];   // [n][k]
__device__ __align__(256) __nv_bfloat16 g_W1[256 * 384];   // [n][k]
__device__ __align__(256) __nv_bfloat16 g_W2[128 * 64];    // [n][k]

// ---------------------------------------------------------------- utils
__device__ __forceinline__ uint32_t smem_u32(const void* p) {
    return (uint32_t)__cvta_generic_to_shared(p);
}
__device__ __forceinline__ void ldsm4(uint32_t& r0, uint32_t& r1, uint32_t& r2,
                                      uint32_t& r3, uint32_t addr) {
    asm volatile("ldmatrix.sync.aligned.m8n8.x4.shared.b16 {%0,%1,%2,%3}, [%4];\n"
                 : "=r"(r0), "=r"(r1), "=r"(r2), "=r"(r3) : "r"(addr));
}
__device__ __forceinline__ void mma16816(float* c, const uint32_t* a,
                                         const uint32_t* b) {
    asm volatile(
        "mma.sync.aligned.m16n8k16.row.col.f32.bf16.bf16.f32 "
        "{%0,%1,%2,%3}, {%4,%5,%6,%7}, {%8,%9}, {%0,%1,%2,%3};\n"
        : "+f"(c[0]), "+f"(c[1]), "+f"(c[2]), "+f"(c[3])
        : "r"(a[0]), "r"(a[1]), "r"(a[2]), "r"(a[3]), "r"(b[0]), "r"(b[1]));
}
__device__ __forceinline__ void cp16(void* sdst, const void* gsrc) {
    asm volatile("cp.async.cg.shared.global [%0], [%1], 16;\n" ::
                 "r"(smem_u32(sdst)), "l"(gsrc));
}

#define BK 32
#define LDP 40  // 80B row stride -> conflict-free ldmatrix / LDS.128 phases
#define HBM_ 64
#define HBN_ 128

// ----------------------------------------------------------------------------
// One-launch weight prep.
// ----------------------------------------------------------------------------
__global__ __launch_bounds__(256)
void prep_weights(const float* __restrict__ dw, const float* __restrict__ w1,
                  const float* __restrict__ w2, __nv_bfloat16* __restrict__ wd,
                  __nv_bfloat16* __restrict__ w1b, __nv_bfloat16* __restrict__ w2b)
{
    const int b = blockIdx.x, tid = threadIdx.x;
    if (b < 256) {
        __shared__ float t[32][33];
        const int n0 = (b & 15) * 32, k0 = (b >> 4) * 32;
        const int tx = tid & 31, ty = tid >> 5;
        for (int r = ty; r < 32; r += 8) t[r][tx] = dw[(k0 + r) * 512 + n0 + tx];
        __syncthreads();
        for (int r = ty; r < 32; r += 8)
            wd[(size_t)(n0 + r) * 512 + k0 + tx] = __float2bfloat16(t[tx][r]);
    } else if (b < 352) {
        const int i = ((b - 256) * 256 + tid) * 4;
        float4 v = *reinterpret_cast<const float4*>(w1 + i);
        *reinterpret_cast<__nv_bfloat162*>(w1b + i)     = __floats2bfloat162_rn(v.x, v.y);
        *reinterpret_cast<__nv_bfloat162*>(w1b + i + 2) = __floats2bfloat162_rn(v.z, v.w);
    } else {
        const int i = ((b - 352) * 256 + tid) * 4;
        float4 v = *reinterpret_cast<const float4*>(w2 + i);
        *reinterpret_cast<__nv_bfloat162*>(w2b + i)     = __floats2bfloat162_rn(v.x, v.y);
        *reinterpret_cast<__nv_bfloat162*>(w2b + i + 2) = __floats2bfloat162_rn(v.z, v.w);
    }
}

// ----------------------------------------------------------------------------
// L1 hi-occ: 64x128x512, A direct from fp32 (LDG+convert+STS, reg double buf),
// B (g_Wd) via cp.async. Warp tile 32x32 (2x4 warps). 3 CTAs/SM.
// ----------------------------------------------------------------------------
__global__ __launch_bounds__(256, 3)
void mma_gemm_l1(const float* __restrict__ A0, const float* __restrict__ A1,
                 const float* __restrict__ A2,
                 const __nv_bfloat16* __restrict__ B,
                 const float* __restrict__ bias,
                 __nv_bfloat16* __restrict__ Out)
{
    constexpr int K = 512;
    __shared__ __align__(16) __nv_bfloat16 As[2][HBM_ * LDP];
    __shared__ __align__(16) __nv_bfloat16 Bs[2][HBN_ * LDP];

    const int tid = threadIdx.x;
    const int warp = tid >> 5, lane = tid & 31;
    const int row0 = blockIdx.y * HBM_;
    const int col0 = blockIdx.x * HBN_;
    const int wm = (warp >> 2) * 32;
    const int wn = (warp & 3) * 32;

    const int s = row0 >> 14;                 // 64 | 16384: block within one input
    const float* Abase = (s == 0) ? A0 : (s == 1) ? A1 : A2;
    const int lrow0 = row0 & (NP - 1);

    // per-stage A: 64 rows x 32 cols fp32 = 256 chunks of 8 floats, 1/thread
    const int ar = tid >> 2;
    const int acc_ = (tid & 3) * 8;

    auto ldgA = [&](int ko, float4 (&ra)[2]) {
        const float* p = Abase + (size_t)(lrow0 + ar) * K + ko + acc_;
        ra[0] = *reinterpret_cast<const float4*>(p);
        ra[1] = *reinterpret_cast<const float4*>(p + 4);
    };
    auto stsA = [&](int buf, const float4 (&ra)[2]) {
        uint4 pk;
        __nv_bfloat162 h;
        h = __floats2bfloat162_rn(ra[0].x, ra[0].y); pk.x = *(const uint32_t*)&h;
        h = __floats2bfloat162_rn(ra[0].z, ra[0].w); pk.y = *(const uint32_t*)&h;
        h = __floats2bfloat162_rn(ra[1].x, ra[1].y); pk.z = *(const uint32_t*)&h;
        h = __floats2bfloat162_rn(ra[1].z, ra[1].w); pk.w = *(const uint32_t*)&h;
        *reinterpret_cast<uint4*>(&As[buf][ar * LDP + acc_]) = pk;
    };
    auto loadB = [&](int buf, int ko) {
        #pragma unroll
        for (int c = 0; c < 2; c++) {
            const int ch = tid + c * 256;
            const int r = ch >> 2, cc = (ch & 3) * 8;
            cp16(&Bs[buf][r * LDP + cc], &B[(size_t)(col0 + r) * K + ko + cc]);
        }
        asm volatile("cp.async.commit_group;\n");
    };

    float acc[2][4][4];
    #pragma unroll
    for (int i = 0; i < 2; i++)
        #pragma unroll
        for (int j = 0; j < 4; j++)
            #pragma unroll
            for (int q = 0; q < 4; q++) acc[i][j][q] = 0.f;

    float4 ra[2];
    ldgA(0, ra);
    loadB(0, 0);

    for (int it = 0; it < 16; it++) {
        const int sb = it & 1;
        stsA(sb, ra);
        if (it + 1 < 16) {
            ldgA((it + 1) * BK, ra);
            loadB((it + 1) & 1, (it + 1) * BK);
            asm volatile("cp.async.wait_group 1;\n");
        } else {
            asm volatile("cp.async.wait_group 0;\n");
        }
        __syncthreads();

        #pragma unroll
        for (int ks = 0; ks < 2; ks++) {
            const int k0 = ks * 16;
            uint32_t a[2][4], b[4][2];
            #pragma unroll
            for (int i = 0; i < 2; i++) {
                int r = wm + i * 16 + (lane & 15);
                int kk = k0 + ((lane >> 4) << 3);
                ldsm4(a[i][0], a[i][1], a[i][2], a[i][3],
                      smem_u32(&As[sb][r * LDP + kk]));
            }
            #pragma unroll
            for (int jp = 0; jp < 2; jp++) {
                int rB = wn + jp * 16 + ((lane >> 4) << 3) + (lane & 7);
                int kk = k0 + (((lane >> 3) & 1) << 3);
                ldsm4(b[2 * jp][0], b[2 * jp][1], b[2 * jp + 1][0], b[2 * jp + 1][1],
                      smem_u32(&Bs[sb][rB * LDP + kk]));
            }
            #pragma unroll
            for (int i = 0; i < 2; i++)
                #pragma unroll
                for (int j = 0; j < 4; j++) mma16816(acc[i][j], a[i], b[j]);
        }
        __syncthreads();
    }

    // epilogue: bias + relu + X1 scatter
    #pragma unroll
    for (int i = 0; i < 2; i++) {
        const int mA = row0 + wm + i * 16 + (lane >> 2);
        #pragma unroll
        for (int j = 0; j < 4; j++) {
            const int nA = col0 + wn + j * 8 + 2 * (lane & 3);
            #pragma unroll
            for (int hh = 0; hh < 2; hh++) {
                const int row = mA + hh * 8;
                const float v0 = fmaxf(acc[i][j][2 * hh]     + bias[nA],     0.f);
                const float v1 = fmaxf(acc[i][j][2 * hh + 1] + bias[nA + 1], 0.f);
                const int pos = nA >> 7, kc = nA & 127;
                const int nl = row & (NP - 1);
                const size_t addr = ((size_t)(nl * 4 + pos)) * 384 + s * 128 + kc;
                *reinterpret_cast<__nv_bfloat162*>(&Out[addr]) =
                    __floats2bfloat162_rn(v0, v1);
            }
        }
    }
}

// ----------------------------------------------------------------------------
// L2 hi-occ: 64x128x384, warp 32x32. (proven R11 config)
// ----------------------------------------------------------------------------
__global__ __launch_bounds__(256, 3)
void mma_gemm_l2(const __nv_bfloat16* __restrict__ A,
                 const __nv_bfloat16* __restrict__ B,
                 const float* __restrict__ bias,
                 __nv_bfloat16* __restrict__ Out)
{
    constexpr int K = 384;
    __shared__ __align__(16) __nv_bfloat16 As[2][HBM_ * LDP];
    __shared__ __align__(16) __nv_bfloat16 Bs[2][HBN_ * LDP];

    const int tid = threadIdx.x;
    const int warp = tid >> 5, lane = tid & 31;
    const int row0 = blockIdx.y * HBM_;
    const int col0 = blockIdx.x * HBN_;
    const int wm = (warp >> 2) * 32;
    const int wn = (warp & 3) * 32;
    const int NIT = K / BK;   // 12

    auto load_stage = [&](int buf, int ko) {
        {
            int r = tid >> 2, cc = (tid & 3) * 8;
            cp16(&As[buf][r * LDP + cc], &A[(size_t)(row0 + r) * K + ko + cc]);
        }
        #pragma unroll
        for (int c = 0; c < 2; c++) {
            int ch = tid + c * 256;
            int r = ch >> 2, cc = (ch & 3) * 8;
            cp16(&Bs[buf][r * LDP + cc], &B[(size_t)(col0 + r) * K + ko + cc]);
        }
        asm volatile("cp.async.commit_group;\n");
    };

    float acc[2][4][4];
    #pragma unroll
    for (int i = 0; i < 2; i++)
        #pragma unroll
        for (int j = 0; j < 4; j++)
            #pragma unroll
            for (int q = 0; q < 4; q++) acc[i][j][q] = 0.f;

    load_stage(0, 0);

    for (int it = 0; it < NIT; it++) {
        if (it + 1 < NIT) {
            load_stage((it + 1) & 1, (it + 1) * BK);
            asm volatile("cp.async.wait_group 1;\n");
        } else {
            asm volatile("cp.async.wait_group 0;\n");
        }
        __syncthreads();

        const int sb = it & 1;
        #pragma unroll
        for (int ks = 0; ks < 2; ks++) {
            const int k0 = ks * 16;
            uint32_t a[2][4], b[4][2];
            #pragma unroll
            for (int i = 0; i < 2; i++) {
                int r = wm + i * 16 + (lane & 15);
                int kk = k0 + ((lane >> 4) << 3);
                ldsm4(a[i][0], a[i][1], a[i][2], a[i][3],
                      smem_u32(&As[sb][r * LDP + kk]));
            }
            #pragma unroll
            for (int jp = 0; jp < 2; jp++) {
                int rB = wn + jp * 16 + ((lane >> 4) << 3) + (lane & 7);
                int kk = k0 + (((lane >> 3) & 1) << 3);
                ldsm4(b[2 * jp][0], b[2 * jp][1], b[2 * jp + 1][0], b[2 * jp + 1][1],
                      smem_u32(&Bs[sb][rB * LDP + kk]));
            }
            #pragma unroll
            for (int i = 0; i < 2; i++)
                #pragma unroll
                for (int j = 0; j < 4; j++) mma16816(acc[i][j], a[i], b[j]);
        }
        __syncthreads();
    }

    #pragma unroll
    for (int i = 0; i < 2; i++) {
        const int mA = row0 + wm + i * 16 + (lane >> 2);
        #pragma unroll
        for (int j = 0; j < 4; j++) {
            const int nA = col0 + wn + j * 8 + 2 * (lane & 3);
            #pragma unroll
            for (int hh = 0; hh < 2; hh++) {
                const int row = mA + hh * 8;
                const float v0 = fmaxf(acc[i][j][2 * hh]     + bias[nA & 63], 0.f);
                const float v1 = fmaxf(acc[i][j][2 * hh + 1] + bias[(nA & 63) + 1], 0.f);
                const int a_ = nA >> 7, c_ = (nA >> 6) & 1, f = nA & 63;
                const int nn = row >> 2, ii = (row >> 1) & 1, jj = row & 1;
                const size_t addr =
                    ((size_t)(nn * 16 + (2 * ii + a_) * 4 + (2 * jj + c_))) * 64 + f;
                *reinterpret_cast<__nv_bfloat162*>(&Out[addr]) =
                    __floats2bfloat162_rn(v0, v1);
            }
        }
    }
}

// ----------------------------------------------------------------------------
// Fused L3+L4 (R12-proven), now 3 CTAs/SM.
// ----------------------------------------------------------------------------
#define F34_SMEM 32768

__global__ __launch_bounds__(256, 3)
void l3_l4_fused(const __nv_bfloat16* __restrict__ A,    // X2
                 const __nv_bfloat16* __restrict__ B,    // W2 [128][64]
                 const float* __restrict__ b2,
                 const float* __restrict__ w3, const float* __restrict__ b3,
                 float* __restrict__ out)
{
    __shared__ __align__(16) uint8_t raw[F34_SMEM];
    __shared__ float ws[384];
    __shared__ float bsm[3];

    __nv_bfloat16* As = reinterpret_cast<__nv_bfloat16*>(raw);              // [2][64*40]
    __nv_bfloat16* Bs = reinterpret_cast<__nv_bfloat16*>(raw + 10240);      // [2][128*40]
    __nv_bfloat16* stage = reinterpret_cast<__nv_bfloat16*>(raw);           // [256][40]
    float* ostage = reinterpret_cast<float*>(raw + 20480);                  // [3072]

    const int tid = threadIdx.x;
    const int warp = tid >> 5, lane = tid & 31;
    const int row0 = blockIdx.x * HBM_;       // X2 row base (4 patches)
    const int wm = (warp >> 2) * 32;
    const int wn = (warp & 3) * 32;

    for (int i = tid; i < 384; i += 256) ws[i] = w3[i];
    if (tid < 3) bsm[tid] = b3[tid];

    auto load_stage = [&](int buf, int ko) {
        {
            int r = tid >> 2, cc = (tid & 3) * 8;
            cp16(&As[buf * (HBM_ * LDP) + r * LDP + cc],
                 &A[(size_t)(row0 + r) * 64 + ko + cc]);
        }
        #pragma unroll
        for (int c = 0; c < 2; c++) {
            int ch = tid + c * 256;
            int r = ch >> 2, cc = (ch & 3) * 8;
            cp16(&Bs[buf * (HBN_ * LDP) + r * LDP + cc],
                 &B[(size_t)r * 64 + ko + cc]);
        }
        asm volatile("cp.async.commit_group;\n");
    };

    float acc[2][4][4];
    #pragma unroll
    for (int i = 0; i < 2; i++)
        #pragma unroll
        for (int j = 0; j < 4; j++)
            #pragma unroll
            for (int q = 0; q < 4; q++) acc[i][j][q] = 0.f;

    load_stage(0, 0);
    load_stage(1, BK);

    #pragma unroll
    for (int it = 0; it < 2; it++) {
        if (it == 0) asm volatile("cp.async.wait_group 1;\n");
        else         asm volatile("cp.async.wait_group 0;\n");
        __syncthreads();

        const int sb = it;
        #pragma unroll
        for (int ks = 0; ks < 2; ks++) {
            const int k0 = ks * 16;
            uint32_t a[2][4], b[4][2];
            #pragma unroll
            for (int i = 0; i < 2; i++) {
                int r = wm + i * 16 + (lane & 15);
                int kk = k0 + ((lane >> 4) << 3);
                ldsm4(a[i][0], a[i][1], a[i][2], a[i][3],
                      smem_u32(&As[sb * (HBM_ * LDP) + r * LDP + kk]));
            }
            #pragma unroll
            for (int jp = 0; jp < 2; jp++) {
                int rB = wn + jp * 16 + ((lane >> 4) << 3) + (lane & 7);
                int kk = k0 + (((lane >> 3) & 1) << 3);
                ldsm4(b[2 * jp][0], b[2 * jp][1], b[2 * jp + 1][0], b[2 * jp + 1][1],
                      smem_u32(&Bs[sb * (HBN_ * LDP) + rB * LDP + kk]));
            }
            #pragma unroll
            for (int i = 0; i < 2; i++)
                #pragma unroll
                for (int j = 0; j < 4; j++) mma16816(acc[i][j], a[i], b[j]);
        }
        __syncthreads();   // after last iter, pipe buffers are dead
    }

    // Phase 2: bias+relu -> stage
    #pragma unroll
    for (int i = 0; i < 2; i++) {
        const int mL = wm + i * 16 + (lane >> 2);
        #pragma unroll
        for (int j = 0; j < 4; j++) {
            const int nA = wn + j * 8 + 2 * (lane & 3);
            const int a_ = nA >> 6, c_ = (nA >> 5) & 1, f = nA & 31;
            #pragma unroll
            for (int hh = 0; hh < 2; hh++) {
                const int r_loc = mL + hh * 8;
                const float v0 = fmaxf(acc[i][j][2 * hh]     + b2[f],     0.f);
                const float v1 = fmaxf(acc[i][j][2 * hh + 1] + b2[f + 1], 0.f);
                const int nl = r_loc >> 4, p = (r_loc >> 2) & 3, q = r_loc & 3;
                const int lrow = nl * 64 + (2 * p + a_) * 8 + (2 * q + c_);
                *reinterpret_cast<__nv_bfloat162*>(&stage[lrow * LDP + f]) =
                    __floats2bfloat162_rn(v0, v1);
            }
        }
    }
    __syncthreads();

    // Phase 3: per-thread X3 row -> 12 sigmoid outputs into ostage
    {
        const int rl = tid;
        uint4 xr[4];
        const uint4* sp = reinterpret_cast<const uint4*>(&stage[rl * LDP]);
        #pragma unroll
        for (int i = 0; i < 4; i++) xr[i] = sp[i];
        __syncthreads();

        float x[32];
        #pragma unroll
        for (int i = 0; i < 16; i++) {
            __nv_bfloat162 pr = reinterpret_cast<const __nv_bfloat162*>(xr)[i];
            float2 f2 = __bfloat1622float2(pr);
            x[2 * i] = f2.x; x[2 * i + 1] = f2.y;
        }
        const int nl = rl >> 6, P = (rl >> 3) & 7, Q = rl & 7;
        const int obase = nl * 768;
        #pragma unroll
        for (int o = 0; o < 12; o++) {
            float accv = bsm[o % 3];
            #pragma unroll
            for (int k = 0; k < 32; k++) accv = fmaf(x[k], ws[o * 32 + k], accv);
            const float v = 1.f / (1.f + __expf(-accv));
            const int a2 = o / 6, c2 = (o / 3) & 1, ch = o % 3;
            ostage[obase + (2 * P + a2) * 48 + (2 * Q + c2) * 3 + ch] = v;
        }
    }
    __syncthreads();

    // Phase 4: coalesced flush — 4 patches * 768 floats contiguous
    float4* gout = reinterpret_cast<float4*>(out + (size_t)blockIdx.x * 3072);
    const float4* so = reinterpret_cast<const float4*>(ostage);
    #pragma unroll
    for (int i = 0; i < 3; i++) gout[tid + i * 256] = so[tid + i * 256];
}

// ---------------------------------------------------------------- host entry
extern "C" void kernel_launch(void* const* d_in, const int* in_sizes, int n_in,
                              void* d_out, int out_size)
{
    const float* in1     = (const float*)d_in[0];
    const float* in2     = (const float*)d_in[1];
    const float* in3     = (const float*)d_in[2];
    const float* dense_w = (const float*)d_in[3];
    const float* dense_b = (const float*)d_in[4];
    const float* w1      = (const float*)d_in[5];
    const float* b1      = (const float*)d_in[6];
    const float* w2      = (const float*)d_in[7];
    const float* b2      = (const float*)d_in[8];
    const float* w3      = (const float*)d_in[9];
    const float* b3      = (const float*)d_in[10];
    float* out           = (float*)d_out;

    __nv_bfloat16 *x1, *x2, *wd, *w1b, *w2b;
    cudaGetSymbolAddress((void**)&x1, g_X1);
    cudaGetSymbolAddress((void**)&x2, g_X2);
    cudaGetSymbolAddress((void**)&wd, g_Wd);
    cudaGetSymbolAddress((void**)&w1b, g_W1);
    cudaGetSymbolAddress((void**)&w2b, g_W2);

    // one-launch weight prep
    prep_weights<<<360, 256>>>(dense_w, w1, w2, wd, w1b, w2b);

    // L1: hi-occ, direct-from-fp32 A, grid (4, 768)
    mma_gemm_l1<<<dim3(512 / HBN_, L1_M / HBM_), 256>>>(in1, in2, in3, wd,
                                                        dense_b, x1);
    // L2: [65536,384] @ w1^T[384,256]  grid (2, 1024)
    mma_gemm_l2<<<dim3(256 / HBN_, X1_ROWS / HBM_), 256>>>(x1, w1b, b1, x2);
    // L3+L4 fused: 4096 blocks of 4 patches
    l3_l4_fused<<<X2_ROWS / HBM_, 256>>>(x2, w2b, b2, w3, b3, out);
}

// round 14
// speedup vs baseline: 1.4919x; 1.0396x over previous
#include <cuda_runtime.h>
#include <cuda_bf16.h>
#include <math.h>
#include <stdint.h>

// ----------------------------------------------------------------------------
// MultiScaleDecoder, mma.sync bf16 (tcgen05 unavailable: harness targets sm_100).
//   prep_weights: dense_w transpose->bf16, w1/w2 ->bf16 (one launch)
//   L1: relu(A @ Wd^T) M=49152 N=512 K=512, A DIRECT from fp32 inputs,
//       FAT tile 128x128 (per-layer finding: L1 wants reuse, not occupancy)
//   L2: relu(X1 @ w1^T) M=65536 N=256 K=384  (hi-occ 64x128, 3 CTAs/SM)
//   L3+L4 FUSED (4 patches/CTA, X3 never in HBM), 3 CTAs/SM, minimal barriers
// ----------------------------------------------------------------------------

#define NP 16384
#define L1_M (3 * NP)                 // 49152
#define X1_ROWS (NP * 4)              // 65536
#define X2_ROWS (NP * 16)             // 262144

__device__ __align__(256) __nv_bfloat16 g_X1[(size_t)X1_ROWS * 384];
__device__ __align__(256) __nv_bfloat16 g_X2[(size_t)X2_ROWS * 64];
__device__ __align__(256) __nv_bfloat16 g_Wd[512 * 512];   // [n][k]
__device__ __align__(256) __nv_bfloat16 g_W1[256 * 384];   // [n][k]
__device__ __align__(256) __nv_bfloat16 g_W2[128 * 64];    // [n][k]

// ---------------------------------------------------------------- utils
__device__ __forceinline__ uint32_t smem_u32(const void* p) {
    return (uint32_t)__cvta_generic_to_shared(p);
}
__device__ __forceinline__ void ldsm4(uint32_t& r0, uint32_t& r1, uint32_t& r2,
                                      uint32_t& r3, uint32_t addr) {
    asm volatile("ldmatrix.sync.aligned.m8n8.x4.shared.b16 {%0,%1,%2,%3}, [%4];\n"
                 : "=r"(r0), "=r"(r1), "=r"(r2), "=r"(r3) : "r"(addr));
}
__device__ __forceinline__ void mma16816(float* c, const uint32_t* a,
                                         const uint32_t* b) {
    asm volatile(
        "mma.sync.aligned.m16n8k16.row.col.f32.bf16.bf16.f32 "
        "{%0,%1,%2,%3}, {%4,%5,%6,%7}, {%8,%9}, {%0,%1,%2,%3};\n"
        : "+f"(c[0]), "+f"(c[1]), "+f"(c[2]), "+f"(c[3])
        : "r"(a[0]), "r"(a[1]), "r"(a[2]), "r"(a[3]), "r"(b[0]), "r"(b[1]));
}
__device__ __forceinline__ void cp16(void* sdst, const void* gsrc) {
    asm volatile("cp.async.cg.shared.global [%0], [%1], 16;\n" ::
                 "r"(smem_u32(sdst)), "l"(gsrc));
}

#define BK 32
#define LDP 40  // 80B row stride -> conflict-free ldmatrix / LDS.128 phases
#define BM 128
#define BN 128
#define HBM_ 64
#define HBN_ 128

// ----------------------------------------------------------------------------
// One-launch weight prep.
// ----------------------------------------------------------------------------
__global__ __launch_bounds__(256)
void prep_weights(const float* __restrict__ dw, const float* __restrict__ w1,
                  const float* __restrict__ w2, __nv_bfloat16* __restrict__ wd,
                  __nv_bfloat16* __restrict__ w1b, __nv_bfloat16* __restrict__ w2b)
{
    const int b = blockIdx.x, tid = threadIdx.x;
    if (b < 256) {
        __shared__ float t[32][33];
        const int n0 = (b & 15) * 32, k0 = (b >> 4) * 32;
        const int tx = tid & 31, ty = tid >> 5;
        for (int r = ty; r < 32; r += 8) t[r][tx] = dw[(k0 + r) * 512 + n0 + tx];
        __syncthreads();
        for (int r = ty; r < 32; r += 8)
            wd[(size_t)(n0 + r) * 512 + k0 + tx] = __float2bfloat16(t[tx][r]);
    } else if (b < 352) {
        const int i = ((b - 256) * 256 + tid) * 4;
        float4 v = *reinterpret_cast<const float4*>(w1 + i);
        *reinterpret_cast<__nv_bfloat162*>(w1b + i)     = __floats2bfloat162_rn(v.x, v.y);
        *reinterpret_cast<__nv_bfloat162*>(w1b + i + 2) = __floats2bfloat162_rn(v.z, v.w);
    } else {
        const int i = ((b - 352) * 256 + tid) * 4;
        float4 v = *reinterpret_cast<const float4*>(w2 + i);
        *reinterpret_cast<__nv_bfloat162*>(w2b + i)     = __floats2bfloat162_rn(v.x, v.y);
        *reinterpret_cast<__nv_bfloat162*>(w2b + i + 2) = __floats2bfloat162_rn(v.z, v.w);
    }
}

// ----------------------------------------------------------------------------
// L1: FAT 128x128x512 tile, A direct from fp32 (LDG+convert+STS, reg double
// buffer), B via cp.async. Warp tile 64x32. (R12-proven config.)
// ----------------------------------------------------------------------------
__global__ __launch_bounds__(256, 2)
void mma_gemm_l1(const float* __restrict__ A0, const float* __restrict__ A1,
                 const float* __restrict__ A2,
                 const __nv_bfloat16* __restrict__ B,
                 const float* __restrict__ bias,
                 __nv_bfloat16* __restrict__ Out)
{
    constexpr int K = 512;
    __shared__ __align__(16) __nv_bfloat16 As[2][BM * LDP];
    __shared__ __align__(16) __nv_bfloat16 Bs[2][BN * LDP];

    const int tid = threadIdx.x;
    const int warp = tid >> 5, lane = tid & 31;
    const int row0 = blockIdx.y * BM;
    const int col0 = blockIdx.x * BN;
    const int wm = (warp >> 2) * 64;
    const int wn = (warp & 3) * 32;

    const int s = row0 >> 14;
    const float* Abase = (s == 0) ? A0 : (s == 1) ? A1 : A2;
    const int lrow0 = row0 & (NP - 1);

    auto ldgA = [&](int ko, float4 (&ra)[2][2]) {
        #pragma unroll
        for (int c = 0; c < 2; c++) {
            const int r = (tid >> 2) + c * 64;
            const int cc = (tid & 3) * 8;
            const float* p = Abase + (size_t)(lrow0 + r) * K + ko + cc;
            ra[c][0] = *reinterpret_cast<const float4*>(p);
            ra[c][1] = *reinterpret_cast<const float4*>(p + 4);
        }
    };
    auto stsA = [&](int buf, const float4 (&ra)[2][2]) {
        #pragma unroll
        for (int c = 0; c < 2; c++) {
            const int r = (tid >> 2) + c * 64;
            const int cc = (tid & 3) * 8;
            uint4 pk;
            __nv_bfloat162 h;
            h = __floats2bfloat162_rn(ra[c][0].x, ra[c][0].y); pk.x = *(const uint32_t*)&h;
            h = __floats2bfloat162_rn(ra[c][0].z, ra[c][0].w); pk.y = *(const uint32_t*)&h;
            h = __floats2bfloat162_rn(ra[c][1].x, ra[c][1].y); pk.z = *(const uint32_t*)&h;
            h = __floats2bfloat162_rn(ra[c][1].z, ra[c][1].w); pk.w = *(const uint32_t*)&h;
            *reinterpret_cast<uint4*>(&As[buf][r * LDP + cc]) = pk;
        }
    };
    auto loadB = [&](int buf, int ko) {
        #pragma unroll
        for (int c = 0; c < 2; c++) {
            const int ch = tid + c * 256;
            const int r = ch >> 2, cc = (ch & 3) * 8;
            cp16(&Bs[buf][r * LDP + cc], &B[(size_t)(col0 + r) * K + ko + cc]);
        }
        asm volatile("cp.async.commit_group;\n");
    };

    float acc[4][4][4];
    #pragma unroll
    for (int i = 0; i < 4; i++)
        #pragma unroll
        for (int j = 0; j < 4; j++)
            #pragma unroll
            for (int q = 0; q < 4; q++) acc[i][j][q] = 0.f;

    float4 ra[2][2];
    ldgA(0, ra);
    loadB(0, 0);

    for (int it = 0; it < 16; it++) {
        const int sb = it & 1;
        stsA(sb, ra);
        if (it + 1 < 16) {
            ldgA((it + 1) * BK, ra);
            loadB((it + 1) & 1, (it + 1) * BK);
            asm volatile("cp.async.wait_group 1;\n");
        } else {
            asm volatile("cp.async.wait_group 0;\n");
        }
        __syncthreads();

        #pragma unroll
        for (int ks = 0; ks < 2; ks++) {
            const int k0 = ks * 16;
            uint32_t a[4][4], b[4][2];
            #pragma unroll
            for (int i = 0; i < 4; i++) {
                int r = wm + i * 16 + (lane & 15);
                int kk = k0 + ((lane >> 4) << 3);
                ldsm4(a[i][0], a[i][1], a[i][2], a[i][3],
                      smem_u32(&As[sb][r * LDP + kk]));
            }
            #pragma unroll
            for (int jp = 0; jp < 2; jp++) {
                int rB = wn + jp * 16 + ((lane >> 4) << 3) + (lane & 7);
                int kk = k0 + (((lane >> 3) & 1) << 3);
                ldsm4(b[2 * jp][0], b[2 * jp][1], b[2 * jp + 1][0], b[2 * jp + 1][1],
                      smem_u32(&Bs[sb][rB * LDP + kk]));
            }
            #pragma unroll
            for (int i = 0; i < 4; i++)
                #pragma unroll
                for (int j = 0; j < 4; j++) mma16816(acc[i][j], a[i], b[j]);
        }
        __syncthreads();
    }

    #pragma unroll
    for (int i = 0; i < 4; i++) {
        const int mA = row0 + wm + i * 16 + (lane >> 2);
        #pragma unroll
        for (int j = 0; j < 4; j++) {
            const int nA = col0 + wn + j * 8 + 2 * (lane & 3);
            #pragma unroll
            for (int hh = 0; hh < 2; hh++) {
                const int row = mA + hh * 8;
                const float v0 = fmaxf(acc[i][j][2 * hh]     + bias[nA],     0.f);
                const float v1 = fmaxf(acc[i][j][2 * hh + 1] + bias[nA + 1], 0.f);
                const int pos = nA >> 7, kc = nA & 127;
                const int nl = row & (NP - 1);
                const size_t addr = ((size_t)(nl * 4 + pos)) * 384 + s * 128 + kc;
                *reinterpret_cast<__nv_bfloat162*>(&Out[addr]) =
                    __floats2bfloat162_rn(v0, v1);
            }
        }
    }
}

// ----------------------------------------------------------------------------
// L2 hi-occ: 64x128x384, warp 32x32, 3 CTAs/SM. (proven)
// ----------------------------------------------------------------------------
__global__ __launch_bounds__(256, 3)
void mma_gemm_l2(const __nv_bfloat16* __restrict__ A,
                 const __nv_bfloat16* __restrict__ B,
                 const float* __restrict__ bias,
                 __nv_bfloat16* __restrict__ Out)
{
    constexpr int K = 384;
    __shared__ __align__(16) __nv_bfloat16 As[2][HBM_ * LDP];
    __shared__ __align__(16) __nv_bfloat16 Bs[2][HBN_ * LDP];

    const int tid = threadIdx.x;
    const int warp = tid >> 5, lane = tid & 31;
    const int row0 = blockIdx.y * HBM_;
    const int col0 = blockIdx.x * HBN_;
    const int wm = (warp >> 2) * 32;
    const int wn = (warp & 3) * 32;
    const int NIT = K / BK;   // 12

    auto load_stage = [&](int buf, int ko) {
        {
            int r = tid >> 2, cc = (tid & 3) * 8;
            cp16(&As[buf][r * LDP + cc], &A[(size_t)(row0 + r) * K + ko + cc]);
        }
        #pragma unroll
        for (int c = 0; c < 2; c++) {
            int ch = tid + c * 256;
            int r = ch >> 2, cc = (ch & 3) * 8;
            cp16(&Bs[buf][r * LDP + cc], &B[(size_t)(col0 + r) * K + ko + cc]);
        }
        asm volatile("cp.async.commit_group;\n");
    };

    float acc[2][4][4];
    #pragma unroll
    for (int i = 0; i < 2; i++)
        #pragma unroll
        for (int j = 0; j < 4; j++)
            #pragma unroll
            for (int q = 0; q < 4; q++) acc[i][j][q] = 0.f;

    load_stage(0, 0);

    for (int it = 0; it < NIT; it++) {
        if (it + 1 < NIT) {
            load_stage((it + 1) & 1, (it + 1) * BK);
            asm volatile("cp.async.wait_group 1;\n");
        } else {
            asm volatile("cp.async.wait_group 0;\n");
        }
        __syncthreads();

        const int sb = it & 1;
        #pragma unroll
        for (int ks = 0; ks < 2; ks++) {
            const int k0 = ks * 16;
            uint32_t a[2][4], b[4][2];
            #pragma unroll
            for (int i = 0; i < 2; i++) {
                int r = wm + i * 16 + (lane & 15);
                int kk = k0 + ((lane >> 4) << 3);
                ldsm4(a[i][0], a[i][1], a[i][2], a[i][3],
                      smem_u32(&As[sb][r * LDP + kk]));
            }
            #pragma unroll
            for (int jp = 0; jp < 2; jp++) {
                int rB = wn + jp * 16 + ((lane >> 4) << 3) + (lane & 7);
                int kk = k0 + (((lane >> 3) & 1) << 3);
                ldsm4(b[2 * jp][0], b[2 * jp][1], b[2 * jp + 1][0], b[2 * jp + 1][1],
                      smem_u32(&Bs[sb][rB * LDP + kk]));
            }
            #pragma unroll
            for (int i = 0; i < 2; i++)
                #pragma unroll
                for (int j = 0; j < 4; j++) mma16816(acc[i][j], a[i], b[j]);
        }
        __syncthreads();
    }

    #pragma unroll
    for (int i = 0; i < 2; i++) {
        const int mA = row0 + wm + i * 16 + (lane >> 2);
        #pragma unroll
        for (int j = 0; j < 4; j++) {
            const int nA = col0 + wn + j * 8 + 2 * (lane & 3);
            #pragma unroll
            for (int hh = 0; hh < 2; hh++) {
                const int row = mA + hh * 8;
                const float v0 = fmaxf(acc[i][j][2 * hh]     + bias[nA & 63], 0.f);
                const float v1 = fmaxf(acc[i][j][2 * hh + 1] + bias[(nA & 63) + 1], 0.f);
                const int a_ = nA >> 7, c_ = (nA >> 6) & 1, f = nA & 63;
                const int nn = row >> 2, ii = (row >> 1) & 1, jj = row & 1;
                const size_t addr =
                    ((size_t)(nn * 16 + (2 * ii + a_) * 4 + (2 * jj + c_))) * 64 + f;
                *reinterpret_cast<__nv_bfloat162*>(&Out[addr]) =
                    __floats2bfloat162_rn(v0, v1);
            }
        }
    }
}

// ----------------------------------------------------------------------------
// Fused L3+L4, 3 CTAs/SM, minimal barriers.
// smem map (32 KB raw):
//   pipe:   As raw[0..10240), Bs raw[10240..30720)          (GEMM phase only)
//   stage:  raw[0..20480)      bf16 [256][40]               (aliases dead pipe)
//   ostage: raw[20480..32768)  fp32 [3072]  — DISJOINT from stage.
// Barriers: 1 (pipe ready) + 1 (pipe dead) + 1 (stage ready) + 1 (ostage ready).
// ----------------------------------------------------------------------------
#define F34_SMEM 32768

__global__ __launch_bounds__(256, 3)
void l3_l4_fused(const __nv_bfloat16* __restrict__ A,    // X2
                 const __nv_bfloat16* __restrict__ B,    // W2 [128][64]
                 const float* __restrict__ b2,
                 const float* __restrict__ w3, const float* __restrict__ b3,
                 float* __restrict__ out)
{
    __shared__ __align__(16) uint8_t raw[F34_SMEM];
    __shared__ float ws[384];
    __shared__ float bsm[3];

    __nv_bfloat16* As = reinterpret_cast<__nv_bfloat16*>(raw);
    __nv_bfloat16* Bs = reinterpret_cast<__nv_bfloat16*>(raw + 10240);
    __nv_bfloat16* stage = reinterpret_cast<__nv_bfloat16*>(raw);
    float* ostage = reinterpret_cast<float*>(raw + 20480);

    const int tid = threadIdx.x;
    const int warp = tid >> 5, lane = tid & 31;
    const int row0 = blockIdx.x * HBM_;
    const int wm = (warp >> 2) * 32;
    const int wn = (warp & 3) * 32;

    for (int i = tid; i < 384; i += 256) ws[i] = w3[i];
    if (tid < 3) bsm[tid] = b3[tid];

    auto load_stage = [&](int buf, int ko) {
        {
            int r = tid >> 2, cc = (tid & 3) * 8;
            cp16(&As[buf * (HBM_ * LDP) + r * LDP + cc],
                 &A[(size_t)(row0 + r) * 64 + ko + cc]);
        }
        #pragma unroll
        for (int c = 0; c < 2; c++) {
            int ch = tid + c * 256;
            int r = ch >> 2, cc = (ch & 3) * 8;
            cp16(&Bs[buf * (HBN_ * LDP) + r * LDP + cc],
                 &B[(size_t)r * 64 + ko + cc]);
        }
    };

    float acc[2][4][4];
    #pragma unroll
    for (int i = 0; i < 2; i++)
        #pragma unroll
        for (int j = 0; j < 4; j++)
            #pragma unroll
            for (int q = 0; q < 4; q++) acc[i][j][q] = 0.f;

    // Load BOTH K-stages up front, one commit, one wait, one barrier.
    load_stage(0, 0);
    load_stage(1, BK);
    asm volatile("cp.async.commit_group;\n");
    asm volatile("cp.async.wait_group 0;\n");
    __syncthreads();

    #pragma unroll
    for (int sb = 0; sb < 2; sb++) {
        #pragma unroll
        for (int ks = 0; ks < 2; ks++) {
            const int k0 = ks * 16;
            uint32_t a[2][4], b[4][2];
            #pragma unroll
            for (int i = 0; i < 2; i++) {
                int r = wm + i * 16 + (lane & 15);
                int kk = k0 + ((lane >> 4) << 3);
                ldsm4(a[i][0], a[i][1], a[i][2], a[i][3],
                      smem_u32(&As[sb * (HBM_ * LDP) + r * LDP + kk]));
            }
            #pragma unroll
            for (int jp = 0; jp < 2; jp++) {
                int rB = wn + jp * 16 + ((lane >> 4) << 3) + (lane & 7);
                int kk = k0 + (((lane >> 3) & 1) << 3);
                ldsm4(b[2 * jp][0], b[2 * jp][1], b[2 * jp + 1][0], b[2 * jp + 1][1],
                      smem_u32(&Bs[sb * (HBN_ * LDP) + rB * LDP + kk]));
            }
            #pragma unroll
            for (int i = 0; i < 2; i++)
                #pragma unroll
                for (int j = 0; j < 4; j++) mma16816(acc[i][j], a[i], b[j]);
        }
    }
    __syncthreads();   // all ldsm done -> pipe buffers dead, stage may overwrite

    // Phase 2: bias+relu -> stage
    #pragma unroll
    for (int i = 0; i < 2; i++) {
        const int mL = wm + i * 16 + (lane >> 2);
        #pragma unroll
        for (int j = 0; j < 4; j++) {
            const int nA = wn + j * 8 + 2 * (lane & 3);
            const int a_ = nA >> 6, c_ = (nA >> 5) & 1, f = nA & 31;
            #pragma unroll
            for (int hh = 0; hh < 2; hh++) {
                const int r_loc = mL + hh * 8;
                const float v0 = fmaxf(acc[i][j][2 * hh]     + b2[f],     0.f);
                const float v1 = fmaxf(acc[i][j][2 * hh + 1] + b2[f + 1], 0.f);
                const int nl = r_loc >> 4, p = (r_loc >> 2) & 3, q = r_loc & 3;
                const int lrow = nl * 64 + (2 * p + a_) * 8 + (2 * q + c_);
                *reinterpret_cast<__nv_bfloat162*>(&stage[lrow * LDP + f]) =
                    __floats2bfloat162_rn(v0, v1);
            }
        }
    }
    __syncthreads();   // stage complete

    // Phase 3: per-thread X3 row -> 12 sigmoid outputs into ostage.
    // stage and ostage are DISJOINT smem regions: no barrier needed between
    // stage reads and ostage writes.
    {
        const int rl = tid;
        uint4 xr[4];
        const uint4* sp = reinterpret_cast<const uint4*>(&stage[rl * LDP]);
        #pragma unroll
        for (int i = 0; i < 4; i++) xr[i] = sp[i];

        float x[32];
        #pragma unroll
        for (int i = 0; i < 16; i++) {
            __nv_bfloat162 pr = reinterpret_cast<const __nv_bfloat162*>(xr)[i];
            float2 f2 = __bfloat1622float2(pr);
            x[2 * i] = f2.x; x[2 * i + 1] = f2.y;
        }
        const int nl = rl >> 6, P = (rl >> 3) & 7, Q = rl & 7;
        const int obase = nl * 768;
        #pragma unroll
        for (int o = 0; o < 12; o++) {
            float accv = bsm[o % 3];
            #pragma unroll
            for (int k = 0; k < 32; k++) accv = fmaf(x[k], ws[o * 32 + k], accv);
            const float v = 1.f / (1.f + __expf(-accv));
            const int a2 = o / 6, c2 = (o / 3) & 1, ch = o % 3;
            ostage[obase + (2 * P + a2) * 48 + (2 * Q + c2) * 3 + ch] = v;
        }
    }
    __syncthreads();   // ostage complete

    // Phase 4: coalesced flush — 4 patches * 768 floats contiguous
    float4* gout = reinterpret_cast<float4*>(out + (size_t)blockIdx.x * 3072);
    const float4* so = reinterpret_cast<const float4*>(ostage);
    #pragma unroll
    for (int i = 0; i < 3; i++) gout[tid + i * 256] = so[tid + i * 256];
}

// ---------------------------------------------------------------- host entry
extern "C" void kernel_launch(void* const* d_in, const int* in_sizes, int n_in,
                              void* d_out, int out_size)
{
    const float* in1     = (const float*)d_in[0];
    const float* in2     = (const float*)d_in[1];
    const float* in3     = (const float*)d_in[2];
    const float* dense_w = (const float*)d_in[3];
    const float* dense_b = (const float*)d_in[4];
    const float* w1      = (const float*)d_in[5];
    const float* b1      = (const float*)d_in[6];
    const float* w2      = (const float*)d_in[7];
    const float* b2      = (const float*)d_in[8];
    const float* w3      = (const float*)d_in[9];
    const float* b3      = (const float*)d_in[10];
    float* out           = (float*)d_out;

    __nv_bfloat16 *x1, *x2, *wd, *w1b, *w2b;
    cudaGetSymbolAddress((void**)&x1, g_X1);
    cudaGetSymbolAddress((void**)&x2, g_X2);
    cudaGetSymbolAddress((void**)&wd, g_Wd);
    cudaGetSymbolAddress((void**)&w1b, g_W1);
    cudaGetSymbolAddress((void**)&w2b, g_W2);

    // one-launch weight prep
    prep_weights<<<360, 256>>>(dense_w, w1, w2, wd, w1b, w2b);

    // L1: fat tile, direct-from-fp32 A, grid (4, 384)
    mma_gemm_l1<<<dim3(512 / BN, L1_M / BM), 256>>>(in1, in2, in3, wd,
                                                    dense_b, x1);
    // L2: [65536,384] @ w1^T[384,256]  grid (2, 1024)
    mma_gemm_l2<<<dim3(256 / HBN_, X1_ROWS / HBM_), 256>>>(x1, w1b, b1, x2);
    // L3+L4 fused: 4096 blocks of 4 patches
    l3_l4_fused<<<X2_ROWS / HBM_, 256>>>(x2, w2b, b2, w3, b3, out);
}

// round 16
// speedup vs baseline: 1.4943x; 1.0016x over previous
#include <cuda_runtime.h>
#include <cuda_bf16.h>
#include <math.h>
#include <stdint.h>

// ----------------------------------------------------------------------------
// MultiScaleDecoder, mma.sync bf16 (tcgen05 unavailable: harness targets sm_100).
//   prep_weights: dense_w transpose->bf16, w1/w2 ->bf16 (one launch)
//   L1: relu(A @ Wd^T) M=49152 N=512 K=512, A DIRECT from fp32 inputs,
//       FAT tile 128x128, 2-stage pipeline (3-stage exceeds 48KB static smem)
//   L2: relu(X1 @ w1^T) M=65536 N=256 K=384, hi-occ 64x128, 3-stage pipeline
//   L3+L4 FUSED (4 patches/CTA, X3 never in HBM), float4 ws reads in tail
// ----------------------------------------------------------------------------

#define NP 16384
#define L1_M (3 * NP)                 // 49152
#define X1_ROWS (NP * 4)              // 65536
#define X2_ROWS (NP * 16)             // 262144

__device__ __align__(256) __nv_bfloat16 g_X1[(size_t)X1_ROWS * 384];
__device__ __align__(256) __nv_bfloat16 g_X2[(size_t)X2_ROWS * 64];
__device__ __align__(256) __nv_bfloat16 g_Wd[512 * 512];   // [n][k]
__device__ __align__(256) __nv_bfloat16 g_W1[256 * 384];   // [n][k]
__device__ __align__(256) __nv_bfloat16 g_W2[128 * 64];    // [n][k]

// ---------------------------------------------------------------- utils
__device__ __forceinline__ uint32_t smem_u32(const void* p) {
    return (uint32_t)__cvta_generic_to_shared(p);
}
__device__ __forceinline__ void ldsm4(uint32_t& r0, uint32_t& r1, uint32_t& r2,
                                      uint32_t& r3, uint32_t addr) {
    asm volatile("ldmatrix.sync.aligned.m8n8.x4.shared.b16 {%0,%1,%2,%3}, [%4];\n"
                 : "=r"(r0), "=r"(r1), "=r"(r2), "=r"(r3) : "r"(addr));
}
__device__ __forceinline__ void mma16816(float* c, const uint32_t* a,
                                         const uint32_t* b) {
    asm volatile(
        "mma.sync.aligned.m16n8k16.row.col.f32.bf16.bf16.f32 "
        "{%0,%1,%2,%3}, {%4,%5,%6,%7}, {%8,%9}, {%0,%1,%2,%3};\n"
        : "+f"(c[0]), "+f"(c[1]), "+f"(c[2]), "+f"(c[3])
        : "r"(a[0]), "r"(a[1]), "r"(a[2]), "r"(a[3]), "r"(b[0]), "r"(b[1]));
}
__device__ __forceinline__ void cp16(void* sdst, const void* gsrc) {
    asm volatile("cp.async.cg.shared.global [%0], [%1], 16;\n" ::
                 "r"(smem_u32(sdst)), "l"(gsrc));
}

#define BK 32
#define LDP 40  // 80B row stride -> conflict-free ldmatrix / LDS.128 phases
#define BM 128
#define BN 128
#define HBM_ 64
#define HBN_ 128

// ----------------------------------------------------------------------------
// One-launch weight prep.
// ----------------------------------------------------------------------------
__global__ __launch_bounds__(256)
void prep_weights(const float* __restrict__ dw, const float* __restrict__ w1,
                  const float* __restrict__ w2, __nv_bfloat16* __restrict__ wd,
                  __nv_bfloat16* __restrict__ w1b, __nv_bfloat16* __restrict__ w2b)
{
    const int b = blockIdx.x, tid = threadIdx.x;
    if (b < 256) {
        __shared__ float t[32][33];
        const int n0 = (b & 15) * 32, k0 = (b >> 4) * 32;
        const int tx = tid & 31, ty = tid >> 5;
        for (int r = ty; r < 32; r += 8) t[r][tx] = dw[(k0 + r) * 512 + n0 + tx];
        __syncthreads();
        for (int r = ty; r < 32; r += 8)
            wd[(size_t)(n0 + r) * 512 + k0 + tx] = __float2bfloat16(t[tx][r]);
    } else if (b < 352) {
        const int i = ((b - 256) * 256 + tid) * 4;
        float4 v = *reinterpret_cast<const float4*>(w1 + i);
        *reinterpret_cast<__nv_bfloat162*>(w1b + i)     = __floats2bfloat162_rn(v.x, v.y);
        *reinterpret_cast<__nv_bfloat162*>(w1b + i + 2) = __floats2bfloat162_rn(v.z, v.w);
    } else {
        const int i = ((b - 352) * 256 + tid) * 4;
        float4 v = *reinterpret_cast<const float4*>(w2 + i);
        *reinterpret_cast<__nv_bfloat162*>(w2b + i)     = __floats2bfloat162_rn(v.x, v.y);
        *reinterpret_cast<__nv_bfloat162*>(w2b + i + 2) = __floats2bfloat162_rn(v.z, v.w);
    }
}

// ----------------------------------------------------------------------------
// L1: FAT 128x128x512, A direct from fp32 (LDG+convert+STS, reg dbl buffer),
// B via 2-stage cp.async pipeline. (R14-proven; 3-stage blows 48KB static.)
// ----------------------------------------------------------------------------
__global__ __launch_bounds__(256, 2)
void mma_gemm_l1(const float* __restrict__ A0, const float* __restrict__ A1,
                 const float* __restrict__ A2,
                 const __nv_bfloat16* __restrict__ B,
                 const float* __restrict__ bias,
                 __nv_bfloat16* __restrict__ Out)
{
    constexpr int K = 512;
    __shared__ __align__(16) __nv_bfloat16 As[2][BM * LDP];
    __shared__ __align__(16) __nv_bfloat16 Bs[2][BN * LDP];

    const int tid = threadIdx.x;
    const int warp = tid >> 5, lane = tid & 31;
    const int row0 = blockIdx.y * BM;
    const int col0 = blockIdx.x * BN;
    const int wm = (warp >> 2) * 64;
    const int wn = (warp & 3) * 32;

    const int s = row0 >> 14;
    const float* Abase = (s == 0) ? A0 : (s == 1) ? A1 : A2;
    const int lrow0 = row0 & (NP - 1);

    auto ldgA = [&](int ko, float4 (&ra)[2][2]) {
        #pragma unroll
        for (int c = 0; c < 2; c++) {
            const int r = (tid >> 2) + c * 64;
            const int cc = (tid & 3) * 8;
            const float* p = Abase + (size_t)(lrow0 + r) * K + ko + cc;
            ra[c][0] = *reinterpret_cast<const float4*>(p);
            ra[c][1] = *reinterpret_cast<const float4*>(p + 4);
        }
    };
    auto stsA = [&](int buf, const float4 (&ra)[2][2]) {
        #pragma unroll
        for (int c = 0; c < 2; c++) {
            const int r = (tid >> 2) + c * 64;
            const int cc = (tid & 3) * 8;
            uint4 pk;
            __nv_bfloat162 h;
            h = __floats2bfloat162_rn(ra[c][0].x, ra[c][0].y); pk.x = *(const uint32_t*)&h;
            h = __floats2bfloat162_rn(ra[c][0].z, ra[c][0].w); pk.y = *(const uint32_t*)&h;
            h = __floats2bfloat162_rn(ra[c][1].x, ra[c][1].y); pk.z = *(const uint32_t*)&h;
            h = __floats2bfloat162_rn(ra[c][1].z, ra[c][1].w); pk.w = *(const uint32_t*)&h;
            *reinterpret_cast<uint4*>(&As[buf][r * LDP + cc]) = pk;
        }
    };
    auto loadB = [&](int buf, int ko) {
        #pragma unroll
        for (int c = 0; c < 2; c++) {
            const int ch = tid + c * 256;
            const int r = ch >> 2, cc = (ch & 3) * 8;
            cp16(&Bs[buf][r * LDP + cc], &B[(size_t)(col0 + r) * K + ko + cc]);
        }
        asm volatile("cp.async.commit_group;\n");
    };

    float acc[4][4][4];
    #pragma unroll
    for (int i = 0; i < 4; i++)
        #pragma unroll
        for (int j = 0; j < 4; j++)
            #pragma unroll
            for (int q = 0; q < 4; q++) acc[i][j][q] = 0.f;

    float4 ra[2][2];
    ldgA(0, ra);
    loadB(0, 0);

    for (int it = 0; it < 16; it++) {
        const int sb = it & 1;
        stsA(sb, ra);
        if (it + 1 < 16) {
            ldgA((it + 1) * BK, ra);
            loadB((it + 1) & 1, (it + 1) * BK);
            asm volatile("cp.async.wait_group 1;\n");
        } else {
            asm volatile("cp.async.wait_group 0;\n");
        }
        __syncthreads();

        #pragma unroll
        for (int ks = 0; ks < 2; ks++) {
            const int k0 = ks * 16;
            uint32_t a[4][4], b[4][2];
            #pragma unroll
            for (int i = 0; i < 4; i++) {
                int r = wm + i * 16 + (lane & 15);
                int kk = k0 + ((lane >> 4) << 3);
                ldsm4(a[i][0], a[i][1], a[i][2], a[i][3],
                      smem_u32(&As[sb][r * LDP + kk]));
            }
            #pragma unroll
            for (int jp = 0; jp < 2; jp++) {
                int rB = wn + jp * 16 + ((lane >> 4) << 3) + (lane & 7);
                int kk = k0 + (((lane >> 3) & 1) << 3);
                ldsm4(b[2 * jp][0], b[2 * jp][1], b[2 * jp + 1][0], b[2 * jp + 1][1],
                      smem_u32(&Bs[sb][rB * LDP + kk]));
            }
            #pragma unroll
            for (int i = 0; i < 4; i++)
                #pragma unroll
                for (int j = 0; j < 4; j++) mma16816(acc[i][j], a[i], b[j]);
        }
        __syncthreads();
    }

    #pragma unroll
    for (int i = 0; i < 4; i++) {
        const int mA = row0 + wm + i * 16 + (lane >> 2);
        #pragma unroll
        for (int j = 0; j < 4; j++) {
            const int nA = col0 + wn + j * 8 + 2 * (lane & 3);
            #pragma unroll
            for (int hh = 0; hh < 2; hh++) {
                const int row = mA + hh * 8;
                const float v0 = fmaxf(acc[i][j][2 * hh]     + bias[nA],     0.f);
                const float v1 = fmaxf(acc[i][j][2 * hh + 1] + bias[nA + 1], 0.f);
                const int pos = nA >> 7, kc = nA & 127;
                const int nl = row & (NP - 1);
                const size_t addr = ((size_t)(nl * 4 + pos)) * 384 + s * 128 + kc;
                *reinterpret_cast<__nv_bfloat162*>(&Out[addr]) =
                    __floats2bfloat162_rn(v0, v1);
            }
        }
    }
}

// ----------------------------------------------------------------------------
// L2 hi-occ: 64x128x384, warp 32x32, 3-stage pipeline (distance 2).
// static smem 46080 B < 48KB; regs ~78 -> 3 CTAs/SM retained (138KB/SM).
// ----------------------------------------------------------------------------
__global__ __launch_bounds__(256, 3)
void mma_gemm_l2(const __nv_bfloat16* __restrict__ A,
                 const __nv_bfloat16* __restrict__ B,
                 const float* __restrict__ bias,
                 __nv_bfloat16* __restrict__ Out)
{
    constexpr int K = 384;
    constexpr int NIT = K / BK;   // 12
    __shared__ __align__(16) __nv_bfloat16 As[3][HBM_ * LDP];
    __shared__ __align__(16) __nv_bfloat16 Bs[3][HBN_ * LDP];

    const int tid = threadIdx.x;
    const int warp = tid >> 5, lane = tid & 31;
    const int row0 = blockIdx.y * HBM_;
    const int col0 = blockIdx.x * HBN_;
    const int wm = (warp >> 2) * 32;
    const int wn = (warp & 3) * 32;

    auto load_stage = [&](int buf, int ko) {
        {
            int r = tid >> 2, cc = (tid & 3) * 8;
            cp16(&As[buf][r * LDP + cc], &A[(size_t)(row0 + r) * K + ko + cc]);
        }
        #pragma unroll
        for (int c = 0; c < 2; c++) {
            int ch = tid + c * 256;
            int r = ch >> 2, cc = (ch & 3) * 8;
            cp16(&Bs[buf][r * LDP + cc], &B[(size_t)(col0 + r) * K + ko + cc]);
        }
        asm volatile("cp.async.commit_group;\n");
    };

    float acc[2][4][4];
    #pragma unroll
    for (int i = 0; i < 2; i++)
        #pragma unroll
        for (int j = 0; j < 4; j++)
            #pragma unroll
            for (int q = 0; q < 4; q++) acc[i][j][q] = 0.f;

    load_stage(0, 0);
    load_stage(1, BK);

    int bcur = 0, bnext = 2;
    for (int it = 0; it < NIT; it++) {
        if (it + 2 < NIT) {
            load_stage(bnext, (it + 2) * BK);
            if (++bnext == 3) bnext = 0;
        }
        if (it < NIT - 2)       asm volatile("cp.async.wait_group 2;\n");
        else if (it == NIT - 2) asm volatile("cp.async.wait_group 1;\n");
        else                    asm volatile("cp.async.wait_group 0;\n");
        __syncthreads();

        #pragma unroll
        for (int ks = 0; ks < 2; ks++) {
            const int k0 = ks * 16;
            uint32_t a[2][4], b[4][2];
            #pragma unroll
            for (int i = 0; i < 2; i++) {
                int r = wm + i * 16 + (lane & 15);
                int kk = k0 + ((lane >> 4) << 3);
                ldsm4(a[i][0], a[i][1], a[i][2], a[i][3],
                      smem_u32(&As[bcur][r * LDP + kk]));
            }
            #pragma unroll
            for (int jp = 0; jp < 2; jp++) {
                int rB = wn + jp * 16 + ((lane >> 4) << 3) + (lane & 7);
                int kk = k0 + (((lane >> 3) & 1) << 3);
                ldsm4(b[2 * jp][0], b[2 * jp][1], b[2 * jp + 1][0], b[2 * jp + 1][1],
                      smem_u32(&Bs[bcur][rB * LDP + kk]));
            }
            #pragma unroll
            for (int i = 0; i < 2; i++)
                #pragma unroll
                for (int j = 0; j < 4; j++) mma16816(acc[i][j], a[i], b[j]);
        }
        __syncthreads();
        if (++bcur == 3) bcur = 0;
    }

    #pragma unroll
    for (int i = 0; i < 2; i++) {
        const int mA = row0 + wm + i * 16 + (lane >> 2);
        #pragma unroll
        for (int j = 0; j < 4; j++) {
            const int nA = col0 + wn + j * 8 + 2 * (lane & 3);
            #pragma unroll
            for (int hh = 0; hh < 2; hh++) {
                const int row = mA + hh * 8;
                const float v0 = fmaxf(acc[i][j][2 * hh]     + bias[nA & 63], 0.f);
                const float v1 = fmaxf(acc[i][j][2 * hh + 1] + bias[(nA & 63) + 1], 0.f);
                const int a_ = nA >> 7, c_ = (nA >> 6) & 1, f = nA & 63;
                const int nn = row >> 2, ii = (row >> 1) & 1, jj = row & 1;
                const size_t addr =
                    ((size_t)(nn * 16 + (2 * ii + a_) * 4 + (2 * jj + c_))) * 64 + f;
                *reinterpret_cast<__nv_bfloat162*>(&Out[addr]) =
                    __floats2bfloat162_rn(v0, v1);
            }
        }
    }
}

// ----------------------------------------------------------------------------
// Fused L3+L4, 3 CTAs/SM, float4 ws reads in the sigmoid tail.
// smem map (32 KB raw):
//   pipe:   As raw[0..10240), Bs raw[10240..30720)   (GEMM phase only)
//   stage:  raw[0..20480)   bf16 [256][40]           (aliases dead pipe)
//   ostage: raw[20480..32768) fp32 [3072]            (disjoint from stage)
// ----------------------------------------------------------------------------
#define F34_SMEM 32768

__global__ __launch_bounds__(256, 3)
void l3_l4_fused(const __nv_bfloat16* __restrict__ A,    // X2
                 const __nv_bfloat16* __restrict__ B,    // W2 [128][64]
                 const float* __restrict__ b2,
                 const float* __restrict__ w3, const float* __restrict__ b3,
                 float* __restrict__ out)
{
    __shared__ __align__(16) uint8_t raw[F34_SMEM];
    __shared__ __align__(16) float ws[384];
    __shared__ float bsm[3];

    __nv_bfloat16* As = reinterpret_cast<__nv_bfloat16*>(raw);
    __nv_bfloat16* Bs = reinterpret_cast<__nv_bfloat16*>(raw + 10240);
    __nv_bfloat16* stage = reinterpret_cast<__nv_bfloat16*>(raw);
    float* ostage = reinterpret_cast<float*>(raw + 20480);

    const int tid = threadIdx.x;
    const int warp = tid >> 5, lane = tid & 31;
    const int row0 = blockIdx.x * HBM_;
    const int wm = (warp >> 2) * 32;
    const int wn = (warp & 3) * 32;

    for (int i = tid; i < 384; i += 256) ws[i] = w3[i];
    if (tid < 3) bsm[tid] = b3[tid];

    auto load_stage = [&](int buf, int ko) {
        {
            int r = tid >> 2, cc = (tid & 3) * 8;
            cp16(&As[buf * (HBM_ * LDP) + r * LDP + cc],
                 &A[(size_t)(row0 + r) * 64 + ko + cc]);
        }
        #pragma unroll
        for (int c = 0; c < 2; c++) {
            int ch = tid + c * 256;
            int r = ch >> 2, cc = (ch & 3) * 8;
            cp16(&Bs[buf * (HBN_ * LDP) + r * LDP + cc],
                 &B[(size_t)r * 64 + ko + cc]);
        }
    };

    float acc[2][4][4];
    #pragma unroll
    for (int i = 0; i < 2; i++)
        #pragma unroll
        for (int j = 0; j < 4; j++)
            #pragma unroll
            for (int q = 0; q < 4; q++) acc[i][j][q] = 0.f;

    load_stage(0, 0);
    load_stage(1, BK);
    asm volatile("cp.async.commit_group;\n");
    asm volatile("cp.async.wait_group 0;\n");
    __syncthreads();

    #pragma unroll
    for (int sb = 0; sb < 2; sb++) {
        #pragma unroll
        for (int ks = 0; ks < 2; ks++) {
            const int k0 = ks * 16;
            uint32_t a[2][4], b[4][2];
            #pragma unroll
            for (int i = 0; i < 2; i++) {
                int r = wm + i * 16 + (lane & 15);
                int kk = k0 + ((lane >> 4) << 3);
                ldsm4(a[i][0], a[i][1], a[i][2], a[i][3],
                      smem_u32(&As[sb * (HBM_ * LDP) + r * LDP + kk]));
            }
            #pragma unroll
            for (int jp = 0; jp < 2; jp++) {
                int rB = wn + jp * 16 + ((lane >> 4) << 3) + (lane & 7);
                int kk = k0 + (((lane >> 3) & 1) << 3);
                ldsm4(b[2 * jp][0], b[2 * jp][1], b[2 * jp + 1][0], b[2 * jp + 1][1],
                      smem_u32(&Bs[sb * (HBN_ * LDP) + rB * LDP + kk]));
            }
            #pragma unroll
            for (int i = 0; i < 2; i++)
                #pragma unroll
                for (int j = 0; j < 4; j++) mma16816(acc[i][j], a[i], b[j]);
        }
    }
    __syncthreads();   // pipe buffers dead -> stage may overwrite

    // Phase 2: bias+relu -> stage
    #pragma unroll
    for (int i = 0; i < 2; i++) {
        const int mL = wm + i * 16 + (lane >> 2);
        #pragma unroll
        for (int j = 0; j < 4; j++) {
            const int nA = wn + j * 8 + 2 * (lane & 3);
            const int a_ = nA >> 6, c_ = (nA >> 5) & 1, f = nA & 31;
            #pragma unroll
            for (int hh = 0; hh < 2; hh++) {
                const int r_loc = mL + hh * 8;
                const float v0 = fmaxf(acc[i][j][2 * hh]     + b2[f],     0.f);
                const float v1 = fmaxf(acc[i][j][2 * hh + 1] + b2[f + 1], 0.f);
                const int nl = r_loc >> 4, p = (r_loc >> 2) & 3, q = r_loc & 3;
                const int lrow = nl * 64 + (2 * p + a_) * 8 + (2 * q + c_);
                *reinterpret_cast<__nv_bfloat162*>(&stage[lrow * LDP + f]) =
                    __floats2bfloat162_rn(v0, v1);
            }
        }
    }
    __syncthreads();   // stage complete

    // Phase 3: per-thread X3 row -> 12 sigmoid outputs (float4 ws reads).
    {
        const int rl = tid;
        uint4 xr[4];
        const uint4* sp = reinterpret_cast<const uint4*>(&stage[rl * LDP]);
        #pragma unroll
        for (int i = 0; i < 4; i++) xr[i] = sp[i];

        float x[32];
        #pragma unroll
        for (int i = 0; i < 16; i++) {
            __nv_bfloat162 pr = reinterpret_cast<const __nv_bfloat162*>(xr)[i];
            float2 f2 = __bfloat1622float2(pr);
            x[2 * i] = f2.x; x[2 * i + 1] = f2.y;
        }
        const int nl = rl >> 6, P = (rl >> 3) & 7, Q = rl & 7;
        const int obase = nl * 768;
        const float4* ws4 = reinterpret_cast<const float4*>(ws);
        #pragma unroll
        for (int o = 0; o < 12; o++) {
            float accv = bsm[o % 3];
            #pragma unroll
            for (int k4 = 0; k4 < 8; k4++) {
                const float4 w = ws4[o * 8 + k4];
                accv = fmaf(x[4 * k4 + 0], w.x, accv);
                accv = fmaf(x[4 * k4 + 1], w.y, accv);
                accv = fmaf(x[4 * k4 + 2], w.z, accv);
                accv = fmaf(x[4 * k4 + 3], w.w, accv);
            }
            const float v = 1.f / (1.f + __expf(-accv));
            const int a2 = o / 6, c2 = (o / 3) & 1, ch = o % 3;
            ostage[obase + (2 * P + a2) * 48 + (2 * Q + c2) * 3 + ch] = v;
        }
    }
    __syncthreads();   // ostage complete

    // Phase 4: coalesced flush — 4 patches * 768 floats contiguous
    float4* gout = reinterpret_cast<float4*>(out + (size_t)blockIdx.x * 3072);
    const float4* so = reinterpret_cast<const float4*>(ostage);
    #pragma unroll
    for (int i = 0; i < 3; i++) gout[tid + i * 256] = so[tid + i * 256];
}

// ---------------------------------------------------------------- host entry
extern "C" void kernel_launch(void* const* d_in, const int* in_sizes, int n_in,
                              void* d_out, int out_size)
{
    const float* in1     = (const float*)d_in[0];
    const float* in2     = (const float*)d_in[1];
    const float* in3     = (const float*)d_in[2];
    const float* dense_w = (const float*)d_in[3];
    const float* dense_b = (const float*)d_in[4];
    const float* w1      = (const float*)d_in[5];
    const float* b1      = (const float*)d_in[6];
    const float* w2      = (const float*)d_in[7];
    const float* b2      = (const float*)d_in[8];
    const float* w3      = (const float*)d_in[9];
    const float* b3      = (const float*)d_in[10];
    float* out           = (float*)d_out;

    __nv_bfloat16 *x1, *x2, *wd, *w1b, *w2b;
    cudaGetSymbolAddress((void**)&x1, g_X1);
    cudaGetSymbolAddress((void**)&x2, g_X2);
    cudaGetSymbolAddress((void**)&wd, g_Wd);
    cudaGetSymbolAddress((void**)&w1b, g_W1);
    cudaGetSymbolAddress((void**)&w2b, g_W2);

    // one-launch weight prep
    prep_weights<<<360, 256>>>(dense_w, w1, w2, wd, w1b, w2b);

    // L1: fat tile, 2-stage, grid (4, 384)
    mma_gemm_l1<<<dim3(512 / BN, L1_M / BM), 256>>>(in1, in2, in3, wd,
                                                    dense_b, x1);
    // L2: [65536,384] @ w1^T[384,256]  grid (2, 1024), 3-stage pipe
    mma_gemm_l2<<<dim3(256 / HBN_, X1_ROWS / HBM_), 256>>>(x1, w1b, b1, x2);
    // L3+L4 fused: 4096 blocks of 4 patches
    l3_l4_fused<<<X2_ROWS / HBM_, 256>>>(x2, w2b, b2, w3, b3, out);
}

// round 17
// speedup vs baseline: 1.5665x; 1.0483x over previous
#include <cuda_runtime.h>
#include <cuda_bf16.h>
#include <math.h>
#include <stdint.h>

// ----------------------------------------------------------------------------
// MultiScaleDecoder, mma.sync bf16 (tcgen05 unavailable: harness targets sm_100).
//   prep_weights: dense_w transpose->bf16, w1/w2 ->bf16 (one launch)
//   L1: relu(A @ Wd^T) M=49152 N=512 K=512, A DIRECT from fp32 inputs, 128x128
//   L2: relu(X1 @ w1^T) M=65536 N=256 K=384, hi-occ 64x128, 3-stage pipeline
//   L3+L4 FUSED: GEMM -> stage -> **L4 as tensor-core mma (N padded 12->16)**
//                -> sigmoid on C fragments -> coalesced flush.
// ----------------------------------------------------------------------------

#define NP 16384
#define L1_M (3 * NP)                 // 49152
#define X1_ROWS (NP * 4)              // 65536
#define X2_ROWS (NP * 16)             // 262144

__device__ __align__(256) __nv_bfloat16 g_X1[(size_t)X1_ROWS * 384];
__device__ __align__(256) __nv_bfloat16 g_X2[(size_t)X2_ROWS * 64];
__device__ __align__(256) __nv_bfloat16 g_Wd[512 * 512];   // [n][k]
__device__ __align__(256) __nv_bfloat16 g_W1[256 * 384];   // [n][k]
__device__ __align__(256) __nv_bfloat16 g_W2[128 * 64];    // [n][k]

// ---------------------------------------------------------------- utils
__device__ __forceinline__ uint32_t smem_u32(const void* p) {
    return (uint32_t)__cvta_generic_to_shared(p);
}
__device__ __forceinline__ void ldsm4(uint32_t& r0, uint32_t& r1, uint32_t& r2,
                                      uint32_t& r3, uint32_t addr) {
    asm volatile("ldmatrix.sync.aligned.m8n8.x4.shared.b16 {%0,%1,%2,%3}, [%4];\n"
                 : "=r"(r0), "=r"(r1), "=r"(r2), "=r"(r3) : "r"(addr));
}
__device__ __forceinline__ void mma16816(float* c, const uint32_t* a,
                                         const uint32_t* b) {
    asm volatile(
        "mma.sync.aligned.m16n8k16.row.col.f32.bf16.bf16.f32 "
        "{%0,%1,%2,%3}, {%4,%5,%6,%7}, {%8,%9}, {%0,%1,%2,%3};\n"
        : "+f"(c[0]), "+f"(c[1]), "+f"(c[2]), "+f"(c[3])
        : "r"(a[0]), "r"(a[1]), "r"(a[2]), "r"(a[3]), "r"(b[0]), "r"(b[1]));
}
__device__ __forceinline__ void cp16(void* sdst, const void* gsrc) {
    asm volatile("cp.async.cg.shared.global [%0], [%1], 16;\n" ::
                 "r"(smem_u32(sdst)), "l"(gsrc));
}

#define BK 32
#define LDP 40  // 80B row stride -> conflict-free ldmatrix / LDS.128 phases
#define BM 128
#define BN 128
#define HBM_ 64
#define HBN_ 128

// ----------------------------------------------------------------------------
// One-launch weight prep.
// ----------------------------------------------------------------------------
__global__ __launch_bounds__(256)
void prep_weights(const float* __restrict__ dw, const float* __restrict__ w1,
                  const float* __restrict__ w2, __nv_bfloat16* __restrict__ wd,
                  __nv_bfloat16* __restrict__ w1b, __nv_bfloat16* __restrict__ w2b)
{
    const int b = blockIdx.x, tid = threadIdx.x;
    if (b < 256) {
        __shared__ float t[32][33];
        const int n0 = (b & 15) * 32, k0 = (b >> 4) * 32;
        const int tx = tid & 31, ty = tid >> 5;
        for (int r = ty; r < 32; r += 8) t[r][tx] = dw[(k0 + r) * 512 + n0 + tx];
        __syncthreads();
        for (int r = ty; r < 32; r += 8)
            wd[(size_t)(n0 + r) * 512 + k0 + tx] = __float2bfloat16(t[tx][r]);
    } else if (b < 352) {
        const int i = ((b - 256) * 256 + tid) * 4;
        float4 v = *reinterpret_cast<const float4*>(w1 + i);
        *reinterpret_cast<__nv_bfloat162*>(w1b + i)     = __floats2bfloat162_rn(v.x, v.y);
        *reinterpret_cast<__nv_bfloat162*>(w1b + i + 2) = __floats2bfloat162_rn(v.z, v.w);
    } else {
        const int i = ((b - 352) * 256 + tid) * 4;
        float4 v = *reinterpret_cast<const float4*>(w2 + i);
        *reinterpret_cast<__nv_bfloat162*>(w2b + i)     = __floats2bfloat162_rn(v.x, v.y);
        *reinterpret_cast<__nv_bfloat162*>(w2b + i + 2) = __floats2bfloat162_rn(v.z, v.w);
    }
}

// ----------------------------------------------------------------------------
// L1: FAT 128x128x512, A direct from fp32 (LDG+convert+STS, reg dbl buffer),
// B via 2-stage cp.async pipeline. (R14/R16-proven, unchanged.)
// ----------------------------------------------------------------------------
__global__ __launch_bounds__(256, 2)
void mma_gemm_l1(const float* __restrict__ A0, const float* __restrict__ A1,
                 const float* __restrict__ A2,
                 const __nv_bfloat16* __restrict__ B,
                 const float* __restrict__ bias,
                 __nv_bfloat16* __restrict__ Out)
{
    constexpr int K = 512;
    __shared__ __align__(16) __nv_bfloat16 As[2][BM * LDP];
    __shared__ __align__(16) __nv_bfloat16 Bs[2][BN * LDP];

    const int tid = threadIdx.x;
    const int warp = tid >> 5, lane = tid & 31;
    const int row0 = blockIdx.y * BM;
    const int col0 = blockIdx.x * BN;
    const int wm = (warp >> 2) * 64;
    const int wn = (warp & 3) * 32;

    const int s = row0 >> 14;
    const float* Abase = (s == 0) ? A0 : (s == 1) ? A1 : A2;
    const int lrow0 = row0 & (NP - 1);

    auto ldgA = [&](int ko, float4 (&ra)[2][2]) {
        #pragma unroll
        for (int c = 0; c < 2; c++) {
            const int r = (tid >> 2) + c * 64;
            const int cc = (tid & 3) * 8;
            const float* p = Abase + (size_t)(lrow0 + r) * K + ko + cc;
            ra[c][0] = *reinterpret_cast<const float4*>(p);
            ra[c][1] = *reinterpret_cast<const float4*>(p + 4);
        }
    };
    auto stsA = [&](int buf, const float4 (&ra)[2][2]) {
        #pragma unroll
        for (int c = 0; c < 2; c++) {
            const int r = (tid >> 2) + c * 64;
            const int cc = (tid & 3) * 8;
            uint4 pk;
            __nv_bfloat162 h;
            h = __floats2bfloat162_rn(ra[c][0].x, ra[c][0].y); pk.x = *(const uint32_t*)&h;
            h = __floats2bfloat162_rn(ra[c][0].z, ra[c][0].w); pk.y = *(const uint32_t*)&h;
            h = __floats2bfloat162_rn(ra[c][1].x, ra[c][1].y); pk.z = *(const uint32_t*)&h;
            h = __floats2bfloat162_rn(ra[c][1].z, ra[c][1].w); pk.w = *(const uint32_t*)&h;
            *reinterpret_cast<uint4*>(&As[buf][r * LDP + cc]) = pk;
        }
    };
    auto loadB = [&](int buf, int ko) {
        #pragma unroll
        for (int c = 0; c < 2; c++) {
            const int ch = tid + c * 256;
            const int r = ch >> 2, cc = (ch & 3) * 8;
            cp16(&Bs[buf][r * LDP + cc], &B[(size_t)(col0 + r) * K + ko + cc]);
        }
        asm volatile("cp.async.commit_group;\n");
    };

    float acc[4][4][4];
    #pragma unroll
    for (int i = 0; i < 4; i++)
        #pragma unroll
        for (int j = 0; j < 4; j++)
            #pragma unroll
            for (int q = 0; q < 4; q++) acc[i][j][q] = 0.f;

    float4 ra[2][2];
    ldgA(0, ra);
    loadB(0, 0);

    for (int it = 0; it < 16; it++) {
        const int sb = it & 1;
        stsA(sb, ra);
        if (it + 1 < 16) {
            ldgA((it + 1) * BK, ra);
            loadB((it + 1) & 1, (it + 1) * BK);
            asm volatile("cp.async.wait_group 1;\n");
        } else {
            asm volatile("cp.async.wait_group 0;\n");
        }
        __syncthreads();

        #pragma unroll
        for (int ks = 0; ks < 2; ks++) {
            const int k0 = ks * 16;
            uint32_t a[4][4], b[4][2];
            #pragma unroll
            for (int i = 0; i < 4; i++) {
                int r = wm + i * 16 + (lane & 15);
                int kk = k0 + ((lane >> 4) << 3);
                ldsm4(a[i][0], a[i][1], a[i][2], a[i][3],
                      smem_u32(&As[sb][r * LDP + kk]));
            }
            #pragma unroll
            for (int jp = 0; jp < 2; jp++) {
                int rB = wn + jp * 16 + ((lane >> 4) << 3) + (lane & 7);
                int kk = k0 + (((lane >> 3) & 1) << 3);
                ldsm4(b[2 * jp][0], b[2 * jp][1], b[2 * jp + 1][0], b[2 * jp + 1][1],
                      smem_u32(&Bs[sb][rB * LDP + kk]));
            }
            #pragma unroll
            for (int i = 0; i < 4; i++)
                #pragma unroll
                for (int j = 0; j < 4; j++) mma16816(acc[i][j], a[i], b[j]);
        }
        __syncthreads();
    }

    #pragma unroll
    for (int i = 0; i < 4; i++) {
        const int mA = row0 + wm + i * 16 + (lane >> 2);
        #pragma unroll
        for (int j = 0; j < 4; j++) {
            const int nA = col0 + wn + j * 8 + 2 * (lane & 3);
            #pragma unroll
            for (int hh = 0; hh < 2; hh++) {
                const int row = mA + hh * 8;
                const float v0 = fmaxf(acc[i][j][2 * hh]     + bias[nA],     0.f);
                const float v1 = fmaxf(acc[i][j][2 * hh + 1] + bias[nA + 1], 0.f);
                const int pos = nA >> 7, kc = nA & 127;
                const int nl = row & (NP - 1);
                const size_t addr = ((size_t)(nl * 4 + pos)) * 384 + s * 128 + kc;
                *reinterpret_cast<__nv_bfloat162*>(&Out[addr]) =
                    __floats2bfloat162_rn(v0, v1);
            }
        }
    }
}

// ----------------------------------------------------------------------------
// L2 hi-occ: 64x128x384, warp 32x32, 3-stage pipeline. (R16-proven, unchanged.)
// ----------------------------------------------------------------------------
__global__ __launch_bounds__(256, 3)
void mma_gemm_l2(const __nv_bfloat16* __restrict__ A,
                 const __nv_bfloat16* __restrict__ B,
                 const float* __restrict__ bias,
                 __nv_bfloat16* __restrict__ Out)
{
    constexpr int K = 384;
    constexpr int NIT = K / BK;   // 12
    __shared__ __align__(16) __nv_bfloat16 As[3][HBM_ * LDP];
    __shared__ __align__(16) __nv_bfloat16 Bs[3][HBN_ * LDP];

    const int tid = threadIdx.x;
    const int warp = tid >> 5, lane = tid & 31;
    const int row0 = blockIdx.y * HBM_;
    const int col0 = blockIdx.x * HBN_;
    const int wm = (warp >> 2) * 32;
    const int wn = (warp & 3) * 32;

    auto load_stage = [&](int buf, int ko) {
        {
            int r = tid >> 2, cc = (tid & 3) * 8;
            cp16(&As[buf][r * LDP + cc], &A[(size_t)(row0 + r) * K + ko + cc]);
        }
        #pragma unroll
        for (int c = 0; c < 2; c++) {
            int ch = tid + c * 256;
            int r = ch >> 2, cc = (ch & 3) * 8;
            cp16(&Bs[buf][r * LDP + cc], &B[(size_t)(col0 + r) * K + ko + cc]);
        }
        asm volatile("cp.async.commit_group;\n");
    };

    float acc[2][4][4];
    #pragma unroll
    for (int i = 0; i < 2; i++)
        #pragma unroll
        for (int j = 0; j < 4; j++)
            #pragma unroll
            for (int q = 0; q < 4; q++) acc[i][j][q] = 0.f;

    load_stage(0, 0);
    load_stage(1, BK);

    int bcur = 0, bnext = 2;
    for (int it = 0; it < NIT; it++) {
        if (it + 2 < NIT) {
            load_stage(bnext, (it + 2) * BK);
            if (++bnext == 3) bnext = 0;
        }
        if (it < NIT - 2)       asm volatile("cp.async.wait_group 2;\n");
        else if (it == NIT - 2) asm volatile("cp.async.wait_group 1;\n");
        else                    asm volatile("cp.async.wait_group 0;\n");
        __syncthreads();

        #pragma unroll
        for (int ks = 0; ks < 2; ks++) {
            const int k0 = ks * 16;
            uint32_t a[2][4], b[4][2];
            #pragma unroll
            for (int i = 0; i < 2; i++) {
                int r = wm + i * 16 + (lane & 15);
                int kk = k0 + ((lane >> 4) << 3);
                ldsm4(a[i][0], a[i][1], a[i][2], a[i][3],
                      smem_u32(&As[bcur][r * LDP + kk]));
            }
            #pragma unroll
            for (int jp = 0; jp < 2; jp++) {
                int rB = wn + jp * 16 + ((lane >> 4) << 3) + (lane & 7);
                int kk = k0 + (((lane >> 3) & 1) << 3);
                ldsm4(b[2 * jp][0], b[2 * jp][1], b[2 * jp + 1][0], b[2 * jp + 1][1],
                      smem_u32(&Bs[bcur][rB * LDP + kk]));
            }
            #pragma unroll
            for (int i = 0; i < 2; i++)
                #pragma unroll
                for (int j = 0; j < 4; j++) mma16816(acc[i][j], a[i], b[j]);
        }
        __syncthreads();
        if (++bcur == 3) bcur = 0;
    }

    #pragma unroll
    for (int i = 0; i < 2; i++) {
        const int mA = row0 + wm + i * 16 + (lane >> 2);
        #pragma unroll
        for (int j = 0; j < 4; j++) {
            const int nA = col0 + wn + j * 8 + 2 * (lane & 3);
            #pragma unroll
            for (int hh = 0; hh < 2; hh++) {
                const int row = mA + hh * 8;
                const float v0 = fmaxf(acc[i][j][2 * hh]     + bias[nA & 63], 0.f);
                const float v1 = fmaxf(acc[i][j][2 * hh + 1] + bias[(nA & 63) + 1], 0.f);
                const int a_ = nA >> 7, c_ = (nA >> 6) & 1, f = nA & 63;
                const int nn = row >> 2, ii = (row >> 1) & 1, jj = row & 1;
                const size_t addr =
                    ((size_t)(nn * 16 + (2 * ii + a_) * 4 + (2 * jj + c_))) * 64 + f;
                *reinterpret_cast<__nv_bfloat162*>(&Out[addr]) =
                    __floats2bfloat162_rn(v0, v1);
            }
        }
    }
}

// ----------------------------------------------------------------------------
// Fused L3+L4. L4 runs on tensor cores: stage[256,32] @ wsb^T (N padded to 16).
// smem map (32 KB raw):
//   pipe:   As raw[0..10240), Bs raw[10240..30720)   (GEMM phase only)
//   stage:  raw[0..20480)   bf16 [256][40]           (aliases dead pipe)
//   ostage: raw[20480..32768) fp32 [3072]            (disjoint from stage)
// wsb: [16][40] bf16 (rows 12-15 garbage -> C cols 12-15 discarded).
// ----------------------------------------------------------------------------
#define F34_SMEM 32768

__global__ __launch_bounds__(256, 3)
void l3_l4_fused(const __nv_bfloat16* __restrict__ A,    // X2
                 const __nv_bfloat16* __restrict__ B,    // W2 [128][64]
                 const float* __restrict__ b2,
                 const float* __restrict__ w3, const float* __restrict__ b3,
                 float* __restrict__ out)
{
    __shared__ __align__(16) uint8_t raw[F34_SMEM];
    __shared__ __align__(16) __nv_bfloat16 wsb[16 * LDP];
    __shared__ float bsm[3];

    __nv_bfloat16* As = reinterpret_cast<__nv_bfloat16*>(raw);
    __nv_bfloat16* Bs = reinterpret_cast<__nv_bfloat16*>(raw + 10240);
    __nv_bfloat16* stage = reinterpret_cast<__nv_bfloat16*>(raw);
    float* ostage = reinterpret_cast<float*>(raw + 20480);

    const int tid = threadIdx.x;
    const int warp = tid >> 5, lane = tid & 31;
    const int row0 = blockIdx.x * HBM_;
    const int wm = (warp >> 2) * 32;
    const int wn = (warp & 3) * 32;

    // Build w3 as bf16 [16][LDP] (only rows 0..11 written; pad rows unused).
    if (tid < 192) {
        const int o = tid >> 4, k = (tid & 15) * 2;
        const float2 v = *reinterpret_cast<const float2*>(w3 + o * 32 + k);
        *reinterpret_cast<__nv_bfloat162*>(&wsb[o * LDP + k]) =
            __floats2bfloat162_rn(v.x, v.y);
    }
    if (tid < 3) bsm[tid] = b3[tid];

    auto load_stage = [&](int buf, int ko) {
        {
            int r = tid >> 2, cc = (tid & 3) * 8;
            cp16(&As[buf * (HBM_ * LDP) + r * LDP + cc],
                 &A[(size_t)(row0 + r) * 64 + ko + cc]);
        }
        #pragma unroll
        for (int c = 0; c < 2; c++) {
            int ch = tid + c * 256;
            int r = ch >> 2, cc = (ch & 3) * 8;
            cp16(&Bs[buf * (HBN_ * LDP) + r * LDP + cc],
                 &B[(size_t)r * 64 + ko + cc]);
        }
    };

    float acc[2][4][4];
    #pragma unroll
    for (int i = 0; i < 2; i++)
        #pragma unroll
        for (int j = 0; j < 4; j++)
            #pragma unroll
            for (int q = 0; q < 4; q++) acc[i][j][q] = 0.f;

    load_stage(0, 0);
    load_stage(1, BK);
    asm volatile("cp.async.commit_group;\n");
    asm volatile("cp.async.wait_group 0;\n");
    __syncthreads();

    #pragma unroll
    for (int sb = 0; sb < 2; sb++) {
        #pragma unroll
        for (int ks = 0; ks < 2; ks++) {
            const int k0 = ks * 16;
            uint32_t a[2][4], b[4][2];
            #pragma unroll
            for (int i = 0; i < 2; i++) {
                int r = wm + i * 16 + (lane & 15);
                int kk = k0 + ((lane >> 4) << 3);
                ldsm4(a[i][0], a[i][1], a[i][2], a[i][3],
                      smem_u32(&As[sb * (HBM_ * LDP) + r * LDP + kk]));
            }
            #pragma unroll
            for (int jp = 0; jp < 2; jp++) {
                int rB = wn + jp * 16 + ((lane >> 4) << 3) + (lane & 7);
                int kk = k0 + (((lane >> 3) & 1) << 3);
                ldsm4(b[2 * jp][0], b[2 * jp][1], b[2 * jp + 1][0], b[2 * jp + 1][1],
                      smem_u32(&Bs[sb * (HBN_ * LDP) + rB * LDP + kk]));
            }
            #pragma unroll
            for (int i = 0; i < 2; i++)
                #pragma unroll
                for (int j = 0; j < 4; j++) mma16816(acc[i][j], a[i], b[j]);
        }
    }
    __syncthreads();   // pipe buffers dead -> stage may overwrite

    // Phase 2: bias+relu -> stage (X3 rows local to these 4 patches)
    #pragma unroll
    for (int i = 0; i < 2; i++) {
        const int mL = wm + i * 16 + (lane >> 2);
        #pragma unroll
        for (int j = 0; j < 4; j++) {
            const int nA = wn + j * 8 + 2 * (lane & 3);
            const int a_ = nA >> 6, c_ = (nA >> 5) & 1, f = nA & 31;
            #pragma unroll
            for (int hh = 0; hh < 2; hh++) {
                const int r_loc = mL + hh * 8;
                const float v0 = fmaxf(acc[i][j][2 * hh]     + b2[f],     0.f);
                const float v1 = fmaxf(acc[i][j][2 * hh + 1] + b2[f + 1], 0.f);
                const int nl = r_loc >> 4, p = (r_loc >> 2) & 3, q = r_loc & 3;
                const int lrow = nl * 64 + (2 * p + a_) * 8 + (2 * q + c_);
                *reinterpret_cast<__nv_bfloat162*>(&stage[lrow * LDP + f]) =
                    __floats2bfloat162_rn(v0, v1);
            }
        }
    }
    __syncthreads();   // stage complete (wsb also visible: written pre-barriers)

    // Phase 3: L4 on tensor cores. Per warp: rows [32*warp, 32*warp+32),
    // C = stage[32,32] @ wsb^T -> [32,16], cols 0..11 valid.
    {
        const int wrow0 = warp * 32;

        // B fragments (k16 x n16) for kt=0,1 — same ldsm pattern as mainloop
        uint32_t bb[2][4];
        #pragma unroll
        for (int kt = 0; kt < 2; kt++) {
            const int rB = ((lane >> 4) << 3) + (lane & 7);
            const int kk = kt * 16 + (((lane >> 3) & 1) << 3);
            ldsm4(bb[kt][0], bb[kt][1], bb[kt][2], bb[kt][3],
                  smem_u32(&wsb[rB * LDP + kk]));
        }

        float c4[2][2][4];
        #pragma unroll
        for (int i = 0; i < 2; i++)
            #pragma unroll
            for (int np = 0; np < 2; np++)
                #pragma unroll
                for (int q = 0; q < 4; q++) c4[i][np][q] = 0.f;

        #pragma unroll
        for (int kt = 0; kt < 2; kt++) {
            uint32_t a[2][4];
            #pragma unroll
            for (int i = 0; i < 2; i++) {
                const int r = wrow0 + i * 16 + (lane & 15);
                const int kk = kt * 16 + ((lane >> 4) << 3);
                ldsm4(a[i][0], a[i][1], a[i][2], a[i][3],
                      smem_u32(&stage[r * LDP + kk]));
            }
            #pragma unroll
            for (int i = 0; i < 2; i++) {
                mma16816(c4[i][0], a[i], &bb[kt][0]);   // cols 0-7
                mma16816(c4[i][1], a[i], &bb[kt][2]);   // cols 8-15
            }
        }

        // sigmoid + scatter valid C entries into ostage
        #pragma unroll
        for (int i = 0; i < 2; i++) {
            #pragma unroll
            for (int np = 0; np < 2; np++) {
                #pragma unroll
                for (int q = 0; q < 4; q++) {
                    const int col = np * 8 + 2 * (lane & 3) + (q & 1);
                    if (col < 12) {
                        const int row = wrow0 + i * 16 + (lane >> 2) + (q >> 1) * 8;
                        const float v =
                            1.f / (1.f + __expf(-(c4[i][np][q] + bsm[col % 3])));
                        const int nl = row >> 6, P = (row >> 3) & 7, Q = row & 7;
                        const int a2 = col / 6, c2 = (col / 3) & 1, ch = col % 3;
                        ostage[nl * 768 + (2 * P + a2) * 48 + (2 * Q + c2) * 3 + ch] = v;
                    }
                }
            }
        }
    }
    __syncthreads();   // ostage complete

    // Phase 4: coalesced flush — 4 patches * 768 floats contiguous
    float4* gout = reinterpret_cast<float4*>(out + (size_t)blockIdx.x * 3072);
    const float4* so = reinterpret_cast<const float4*>(ostage);
    #pragma unroll
    for (int i = 0; i < 3; i++) gout[tid + i * 256] = so[tid + i * 256];
}

// ---------------------------------------------------------------- host entry
extern "C" void kernel_launch(void* const* d_in, const int* in_sizes, int n_in,
                              void* d_out, int out_size)
{
    const float* in1     = (const float*)d_in[0];
    const float* in2     = (const float*)d_in[1];
    const float* in3     = (const float*)d_in[2];
    const float* dense_w = (const float*)d_in[3];
    const float* dense_b = (const float*)d_in[4];
    const float* w1      = (const float*)d_in[5];
    const float* b1      = (const float*)d_in[6];
    const float* w2      = (const float*)d_in[7];
    const float* b2      = (const float*)d_in[8];
    const float* w3      = (const float*)d_in[9];
    const float* b3      = (const float*)d_in[10];
    float* out           = (float*)d_out;

    __nv_bfloat16 *x1, *x2, *wd, *w1b, *w2b;
    cudaGetSymbolAddress((void**)&x1, g_X1);
    cudaGetSymbolAddress((void**)&x2, g_X2);
    cudaGetSymbolAddress((void**)&wd, g_Wd);
    cudaGetSymbolAddress((void**)&w1b, g_W1);
    cudaGetSymbolAddress((void**)&w2b, g_W2);

    // one-launch weight prep
    prep_weights<<<360, 256>>>(dense_w, w1, w2, wd, w1b, w2b);

    // L1: fat tile, 2-stage, grid (4, 384)
    mma_gemm_l1<<<dim3(512 / BN, L1_M / BM), 256>>>(in1, in2, in3, wd,
                                                    dense_b, x1);
    // L2: [65536,384] @ w1^T[384,256]  grid (2, 1024), 3-stage pipe
    mma_gemm_l2<<<dim3(256 / HBN_, X1_ROWS / HBM_), 256>>>(x1, w1b, b1, x2);
    // L3+L4 fused: 4096 blocks of 4 patches
    l3_l4_fused<<<X2_ROWS / HBM_, 256>>>(x2, w2b, b2, w3, b3, out);
}